// round 3
// baseline (speedup 1.0000x reference)
#include <cuda_runtime.h>
#include <cuda_bf16.h>
#include <cstdint>
#include <cstddef>

#define NNODES 100000
#define NPAD   100096           // 782 * 128
#define NEDGES 1600000
#define NBM    782              // NPAD / 128

// -------- scratch (device globals; no allocations allowed) --------
__device__ __align__(16) float g_agg1[(size_t)NPAD * 128];   // sum of x over in-edges
__device__ __align__(16) float g_in1 [(size_t)NPAD * 256];   // [mean || x]
__device__ __align__(16) float g_h   [(size_t)NPAD * 256];   // layer-1 output
__device__ __align__(16) float g_p   [(size_t)NPAD * 128];   // h @ W2l^T
__device__ __align__(16) float g_agg2[(size_t)NPAD * 128];   // sum of p over in-edges
__device__ __align__(16) float g_deg [NPAD];
__device__ __align__(16) float g_w1  [256 * 256];            // [W1l || W1r] rows=out dim
__device__ __align__(16) float g_w2  [256 * 256];            // [W2l ; W2r]  rows=out dim
__device__ int g_is64;                                       // edge_index stored as int64?

// -------- detect edge_index element width (int32 vs int64) --------
// int64 layout: odd 32-bit words are high words of values < 2^31 -> all zero.
__global__ void detect_kernel(const int* __restrict__ ei32) {
    __shared__ int sOr;
    if (threadIdx.x == 0) sOr = 0;
    __syncthreads();
    int acc = 0;
    for (int i = threadIdx.x; i < 2048; i += blockDim.x) acc |= ei32[2 * i + 1];
    atomicOr(&sOr, acc);
    __syncthreads();
    if (threadIdx.x == 0) g_is64 = (sOr == 0) ? 1 : 0;
}

// -------- zero scratch accumulators --------
__global__ void zero_kernel() {
    size_t i = (size_t)blockIdx.x * blockDim.x + threadIdx.x;
    size_t stride = (size_t)gridDim.x * blockDim.x;
    float4 z = make_float4(0.f, 0.f, 0.f, 0.f);
    float4* a1 = (float4*)g_agg1;
    float4* a2 = (float4*)g_agg2;
    for (size_t q = i; q < (size_t)NPAD * 32; q += stride) { a1[q] = z; a2[q] = z; }
    for (size_t q = i; q < (size_t)NPAD; q += stride) g_deg[q] = 0.f;
}

// -------- build concatenated weight matrices --------
__global__ void prep_weights(const float* __restrict__ W1l, const float* __restrict__ W1r,
                             const float* __restrict__ W2l, const float* __restrict__ W2r) {
    int j = blockIdx.x;    // 0..255 output dim
    int k = threadIdx.x;   // 0..255 input dim
    g_w1[j * 256 + k] = (k < 128) ? W1l[j * 128 + k] : W1r[j * 128 + (k - 128)];
    g_w2[j * 256 + k] = (j < 128) ? W2l[j * 256 + k] : W2r[(j - 128) * 256 + k];
}

// -------- edge aggregation: one warp per edge, vectorized L2 reduction --------
__global__ void agg_kernel(const float* __restrict__ xsrc,
                           const void* __restrict__ ei,
                           int phase) {
    int gw = (int)(((size_t)blockIdx.x * blockDim.x + threadIdx.x) >> 5);
    int lane = threadIdx.x & 31;
    if (gw >= NEDGES) return;
    int s, t;
    if (g_is64) {
        const long long* e64 = (const long long*)ei;
        s = (int)e64[gw];
        t = (int)e64[(size_t)NEDGES + gw];
    } else {
        const int* e32 = (const int*)ei;
        s = e32[gw];
        t = e32[(size_t)NEDGES + gw];
    }
    if ((unsigned)s >= NNODES || (unsigned)t >= NNODES) return;  // trap guard
    const float* src = (phase == 0) ? xsrc : g_p;
    float*       dst = (phase == 0) ? g_agg1 : g_agg2;
    float4 v = ((const float4*)(src + ((size_t)s << 7)))[lane];
    float* d = dst + ((size_t)t << 7) + ((size_t)lane << 2);
    asm volatile("red.global.add.v4.f32 [%0], {%1,%2,%3,%4};"
                 :: "l"(d), "f"(v.x), "f"(v.y), "f"(v.z), "f"(v.w) : "memory");
    if (phase == 0 && lane == 0) atomicAdd(g_deg + t, 1.0f);
}

// -------- build [mean || x] (pads zeroed) --------
__global__ void build_in1(const float* __restrict__ x) {
    size_t idx = (size_t)blockIdx.x * 256 + threadIdx.x;   // float4 index
    if (idx >= (size_t)NPAD * 64) return;
    int m = (int)(idx >> 6);
    int q = (int)(idx & 63);
    float4 v;
    if (q < 32) {
        float rdeg = 1.0f / fmaxf(g_deg[m], 1.0f);
        float4 a = ((const float4*)g_agg1)[(size_t)m * 32 + q];
        v = make_float4(a.x * rdeg, a.y * rdeg, a.z * rdeg, a.w * rdeg);
    } else {
        if (m < NNODES) v = ((const float4*)x)[(size_t)m * 32 + (q - 32)];
        else            v = make_float4(0.f, 0.f, 0.f, 0.f);
    }
    ((float4*)g_in1)[idx] = v;
}

// -------- SGEMM: C[M,256] = A[M,256] @ W[256,256]^T, packed f32x2 FMA --------
// 128x128 block tile, 8x8 microtile, BK=16, 256 threads.
__global__ __launch_bounds__(256) void gemm256(int layer,
                                               const float* __restrict__ b1v,
                                               const float* __restrict__ b2v,
                                               float* __restrict__ dout) {
    __shared__ __align__(16) float2 sA2[16][128];   // duplicated (a,a) pairs, 16KB
    __shared__ __align__(16) float  sB [16][128];   // 8KB

    const float* A = (layer == 1) ? g_in1 : g_h;
    const float* W = (layer == 1) ? g_w1 : g_w2;
    int by = blockIdx.y;
    const float* biasp; float* outp; int ldo, mlim, relu;
    if (layer == 1) {
        biasp = by ? (b1v + 128) : b1v;
        outp = g_h + by * 128; ldo = 256; mlim = NPAD; relu = 1;
    } else {
        biasp = by ? b2v : (const float*)0;
        outp = by ? dout : g_p; ldo = 128; mlim = by ? NNODES : NPAD; relu = 0;
    }

    int row0 = blockIdx.x * 128;
    int n0   = by * 128;
    int tid  = threadIdx.x;
    int rm   = (tid >> 4) << 3;   // 0..120
    int cn   = (tid & 15) << 3;   // 0..120

    unsigned long long acc[8][4];
#pragma unroll
    for (int i = 0; i < 8; ++i)
#pragma unroll
        for (int j = 0; j < 4; ++j) acc[i][j] = 0ULL;

    for (int kt = 0; kt < 16; ++kt) {
#pragma unroll
        for (int l = 0; l < 2; ++l) {
            int fid = tid + l * 256;      // 0..511
            int m   = fid >> 2;           // 0..127
            int kk  = (fid & 3) << 2;     // 0,4,8,12
            float4 v = *(const float4*)(A + (size_t)(row0 + m) * 256 + kt * 16 + kk);
            sA2[kk + 0][m] = make_float2(v.x, v.x);
            sA2[kk + 1][m] = make_float2(v.y, v.y);
            sA2[kk + 2][m] = make_float2(v.z, v.z);
            sA2[kk + 3][m] = make_float2(v.w, v.w);
            float4 w = *(const float4*)(W + (size_t)(n0 + m) * 256 + kt * 16 + kk);
            sB[kk + 0][m] = w.x; sB[kk + 1][m] = w.y;
            sB[kk + 2][m] = w.z; sB[kk + 3][m] = w.w;
        }
        __syncthreads();
#pragma unroll
        for (int k = 0; k < 16; ++k) {
            ulonglong2 aa0 = *(const ulonglong2*)&sA2[k][rm];
            ulonglong2 aa1 = *(const ulonglong2*)&sA2[k][rm + 2];
            ulonglong2 aa2 = *(const ulonglong2*)&sA2[k][rm + 4];
            ulonglong2 aa3 = *(const ulonglong2*)&sA2[k][rm + 6];
            ulonglong2 bb0 = *(const ulonglong2*)&sB[k][cn];
            ulonglong2 bb1 = *(const ulonglong2*)&sB[k][cn + 4];
            unsigned long long ar[8] = {aa0.x, aa0.y, aa1.x, aa1.y,
                                        aa2.x, aa2.y, aa3.x, aa3.y};
            unsigned long long br[4] = {bb0.x, bb0.y, bb1.x, bb1.y};
#pragma unroll
            for (int i = 0; i < 8; ++i)
#pragma unroll
                for (int j = 0; j < 4; ++j)
                    asm("fma.rn.f32x2 %0, %1, %2, %3;"
                        : "=l"(acc[i][j])
                        : "l"(ar[i]), "l"(br[j]), "l"(acc[i][j]));
        }
        __syncthreads();
    }

    // epilogue
#pragma unroll
    for (int i = 0; i < 8; ++i) {
        int gm = row0 + rm + i;
        if (gm >= mlim) continue;
        float* orow = outp + (size_t)gm * ldo + cn;
#pragma unroll
        for (int j = 0; j < 4; ++j) {
            float2 c = *reinterpret_cast<float2*>(&acc[i][j]);
            int cc = 2 * j;
            if (biasp) { c.x += biasp[cn + cc]; c.y += biasp[cn + cc + 1]; }
            if (relu)  { c.x = fmaxf(c.x, 0.f); c.y = fmaxf(c.y, 0.f); }
            *reinterpret_cast<float2*>(orow + cc) = c;
        }
    }
}

// -------- final: out = r + agg2/deg --------
__global__ void final_kernel(float* __restrict__ out) {
    size_t idx = (size_t)blockIdx.x * 256 + threadIdx.x;   // float4 index
    if (idx >= (size_t)NNODES * 32) return;
    int m = (int)(idx >> 5);
    float rdeg = 1.0f / fmaxf(g_deg[m], 1.0f);
    float4 o = ((float4*)out)[idx];
    float4 a = ((const float4*)g_agg2)[idx];
    o.x += a.x * rdeg; o.y += a.y * rdeg;
    o.z += a.z * rdeg; o.w += a.w * rdeg;
    ((float4*)out)[idx] = o;
}

extern "C" void kernel_launch(void* const* d_in, const int* in_sizes, int n_in,
                              void* d_out, int out_size) {
    const float* x   = (const float*)d_in[0];
    const void*  ei  = d_in[1];
    const float* W1l = (const float*)d_in[2];
    const float* b1  = (const float*)d_in[3];
    const float* W1r = (const float*)d_in[4];
    const float* W2l = (const float*)d_in[5];
    const float* b2  = (const float*)d_in[6];
    const float* W2r = (const float*)d_in[7];
    float* out = (float*)d_out;

    detect_kernel<<<1, 256>>>((const int*)ei);
    zero_kernel<<<2048, 256>>>();
    prep_weights<<<256, 256>>>(W1l, W1r, W2l, W2r);

    // layer 1: aggregate x, then fused GEMM -> h = relu([mean||x] @ W1cat^T + b1)
    agg_kernel<<<NEDGES / 8, 256>>>(x, ei, 0);
    build_in1<<<(unsigned)(((size_t)NPAD * 64 + 255) / 256), 256>>>(x);
    gemm256<<<dim3(NBM, 2), 256>>>(1, b1, b2, out);

    // layer 2: GEMM first (p = h@W2l^T, r = h@W2r^T + b2 -> d_out), then aggregate p
    gemm256<<<dim3(NBM, 2), 256>>>(2, b1, b2, out);
    agg_kernel<<<NEDGES / 8, 256>>>(x, ei, 1);
    final_kernel<<<(unsigned)(((size_t)NNODES * 32 + 255) / 256), 256>>>(out);
}

// round 4
// speedup vs baseline: 1.1084x; 1.1084x over previous
#include <cuda_runtime.h>
#include <cuda_bf16.h>
#include <cstdint>
#include <cstddef>

#define NNODES 100000
#define NPAD   100096           // 782 * 128
#define NEDGES 1600000
#define NBM    782              // NPAD / 128

// -------- scratch (device globals; no allocations allowed) --------
__device__ __align__(16) float g_agg1[(size_t)NPAD * 128];   // sum of x over in-edges
__device__ __align__(16) float g_in1 [(size_t)NPAD * 256];   // [mean || x]
__device__ __align__(16) float g_h   [(size_t)NPAD * 256];   // layer-1 output
__device__ __align__(16) float g_p   [(size_t)NPAD * 128];   // h @ W2l^T
__device__ __align__(16) float g_agg2[(size_t)NPAD * 128];   // sum of p over in-edges
__device__ __align__(16) float g_deg [NPAD];
__device__ __align__(16) float g_w1  [256 * 256];            // [W1l || W1r] rows=out dim
__device__ __align__(16) float g_w2  [256 * 256];            // [W2l ; W2r]  rows=out dim
__device__ int g_is64;                                       // edge_index stored as int64?

// -------- detect edge_index element width (int32 vs int64) --------
__global__ void detect_kernel(const int* __restrict__ ei32) {
    __shared__ int sOr;
    if (threadIdx.x == 0) sOr = 0;
    __syncthreads();
    int acc = 0;
    for (int i = threadIdx.x; i < 2048; i += blockDim.x) acc |= ei32[2 * i + 1];
    atomicOr(&sOr, acc);
    __syncthreads();
    if (threadIdx.x == 0) g_is64 = (sOr == 0) ? 1 : 0;
}

// -------- zero scratch accumulators --------
__global__ void zero_kernel() {
    size_t i = (size_t)blockIdx.x * blockDim.x + threadIdx.x;
    size_t stride = (size_t)gridDim.x * blockDim.x;
    float4 z = make_float4(0.f, 0.f, 0.f, 0.f);
    float4* a1 = (float4*)g_agg1;
    float4* a2 = (float4*)g_agg2;
    for (size_t q = i; q < (size_t)NPAD * 32; q += stride) { a1[q] = z; a2[q] = z; }
    for (size_t q = i; q < (size_t)NPAD; q += stride) g_deg[q] = 0.f;
}

// -------- build concatenated weight matrices --------
__global__ void prep_weights(const float* __restrict__ W1l, const float* __restrict__ W1r,
                             const float* __restrict__ W2l, const float* __restrict__ W2r) {
    int j = blockIdx.x;    // 0..255 output dim
    int k = threadIdx.x;   // 0..255 input dim
    g_w1[j * 256 + k] = (k < 128) ? W1l[j * 128 + k] : W1r[j * 128 + (k - 128)];
    g_w2[j * 256 + k] = (j < 128) ? W2l[j * 256 + k] : W2r[(j - 128) * 256 + k];
}

// -------- edge aggregation: one warp per edge, vectorized L2 reduction --------
__global__ void agg_kernel(const float* __restrict__ xsrc,
                           const void* __restrict__ ei,
                           int phase) {
    int gw = (int)(((size_t)blockIdx.x * blockDim.x + threadIdx.x) >> 5);
    int lane = threadIdx.x & 31;
    if (gw >= NEDGES) return;
    int s, t;
    if (g_is64) {
        const long long* e64 = (const long long*)ei;
        s = (int)e64[gw];
        t = (int)e64[(size_t)NEDGES + gw];
    } else {
        const int* e32 = (const int*)ei;
        s = e32[gw];
        t = e32[(size_t)NEDGES + gw];
    }
    if ((unsigned)s >= NNODES || (unsigned)t >= NNODES) return;  // trap guard
    const float* src = (phase == 0) ? xsrc : g_p;
    float*       dst = (phase == 0) ? g_agg1 : g_agg2;
    float4 v = ((const float4*)(src + ((size_t)s << 7)))[lane];
    float* d = dst + ((size_t)t << 7) + ((size_t)lane << 2);
    asm volatile("red.global.add.v4.f32 [%0], {%1,%2,%3,%4};"
                 :: "l"(d), "f"(v.x), "f"(v.y), "f"(v.z), "f"(v.w) : "memory");
    if (phase == 0 && lane == 0) atomicAdd(g_deg + t, 1.0f);
}

// -------- build [mean || x] (pads zeroed) --------
__global__ void build_in1(const float* __restrict__ x) {
    size_t idx = (size_t)blockIdx.x * 256 + threadIdx.x;   // float4 index
    if (idx >= (size_t)NPAD * 64) return;
    int m = (int)(idx >> 6);
    int q = (int)(idx & 63);
    float4 v;
    if (q < 32) {
        float rdeg = 1.0f / fmaxf(g_deg[m], 1.0f);
        float4 a = ((const float4*)g_agg1)[(size_t)m * 32 + q];
        v = make_float4(a.x * rdeg, a.y * rdeg, a.z * rdeg, a.w * rdeg);
    } else {
        if (m < NNODES) v = ((const float4*)x)[(size_t)m * 32 + (q - 32)];
        else            v = make_float4(0.f, 0.f, 0.f, 0.f);
    }
    ((float4*)g_in1)[idx] = v;
}

// -------- SGEMM: C[M,256] = A[M,256] @ W[256,256]^T, packed f32x2 FMA --------
// 128x128 block tile, 8x8 microtile, BK=16, 256 threads.
// Double-buffered smem with register staging: LDG for tile kt+1 issued before
// compute on tile kt; one __syncthreads per kt.
__global__ __launch_bounds__(256, 2) void gemm256(int layer,
                                                  const float* __restrict__ b1v,
                                                  const float* __restrict__ b2v,
                                                  float* __restrict__ dout) {
    __shared__ __align__(16) float2 sA2[2][16][128];   // duplicated (a,a) pairs, 2x16KB
    __shared__ __align__(16) float  sB [2][16][128];   // 2x8KB

    const float* A = (layer == 1) ? g_in1 : g_h;
    const float* W = (layer == 1) ? g_w1 : g_w2;
    int by = blockIdx.y;
    const float* biasp; float* outp; int ldo, mlim, relu;
    if (layer == 1) {
        biasp = by ? (b1v + 128) : b1v;
        outp = g_h + by * 128; ldo = 256; mlim = NPAD; relu = 1;
    } else {
        biasp = by ? b2v : (const float*)0;
        outp = by ? dout : g_p; ldo = 128; mlim = by ? NNODES : NPAD; relu = 0;
    }

    int row0 = blockIdx.x * 128;
    int n0   = by * 128;
    int tid  = threadIdx.x;
    int rm   = (tid >> 4) << 3;   // 0..120
    int cn   = (tid & 15) << 3;   // 0..120

    // load-thread mapping: m0 = tid>>2 (0..63), m1 = m0+64, kk = (tid&3)*4
    int m0 = tid >> 2;
    int m1 = m0 + 64;
    int kk = (tid & 3) << 2;
    const float* Arow0 = A + (size_t)(row0 + m0) * 256 + kk;
    const float* Arow1 = A + (size_t)(row0 + m1) * 256 + kk;
    const float* Wrow0 = W + (size_t)(n0 + m0) * 256 + kk;
    const float* Wrow1 = W + (size_t)(n0 + m1) * 256 + kk;

    unsigned long long acc[8][4];
#pragma unroll
    for (int i = 0; i < 8; ++i)
#pragma unroll
        for (int j = 0; j < 4; ++j) acc[i][j] = 0ULL;

    // prologue: load kt=0, store to stage 0
    float4 va0 = *(const float4*)(Arow0);
    float4 va1 = *(const float4*)(Arow1);
    float4 vb0 = *(const float4*)(Wrow0);
    float4 vb1 = *(const float4*)(Wrow1);
    {
        sA2[0][kk + 0][m0] = make_float2(va0.x, va0.x);
        sA2[0][kk + 1][m0] = make_float2(va0.y, va0.y);
        sA2[0][kk + 2][m0] = make_float2(va0.z, va0.z);
        sA2[0][kk + 3][m0] = make_float2(va0.w, va0.w);
        sA2[0][kk + 0][m1] = make_float2(va1.x, va1.x);
        sA2[0][kk + 1][m1] = make_float2(va1.y, va1.y);
        sA2[0][kk + 2][m1] = make_float2(va1.z, va1.z);
        sA2[0][kk + 3][m1] = make_float2(va1.w, va1.w);
        sB[0][kk + 0][m0] = vb0.x; sB[0][kk + 1][m0] = vb0.y;
        sB[0][kk + 2][m0] = vb0.z; sB[0][kk + 3][m0] = vb0.w;
        sB[0][kk + 0][m1] = vb1.x; sB[0][kk + 1][m1] = vb1.y;
        sB[0][kk + 2][m1] = vb1.z; sB[0][kk + 3][m1] = vb1.w;
    }

    for (int kt = 0; kt < 16; ++kt) {
        int st = kt & 1;
        __syncthreads();   // stage st fully written, stage st^1 fully consumed

        // issue loads for next tile (latency hidden under compute below)
        if (kt < 15) {
            int off = (kt + 1) * 16;
            va0 = *(const float4*)(Arow0 + off);
            va1 = *(const float4*)(Arow1 + off);
            vb0 = *(const float4*)(Wrow0 + off);
            vb1 = *(const float4*)(Wrow1 + off);
        }

#pragma unroll
        for (int k = 0; k < 16; ++k) {
            ulonglong2 aa0 = *(const ulonglong2*)&sA2[st][k][rm];
            ulonglong2 aa1 = *(const ulonglong2*)&sA2[st][k][rm + 2];
            ulonglong2 aa2 = *(const ulonglong2*)&sA2[st][k][rm + 4];
            ulonglong2 aa3 = *(const ulonglong2*)&sA2[st][k][rm + 6];
            ulonglong2 bb0 = *(const ulonglong2*)&sB[st][k][cn];
            ulonglong2 bb1 = *(const ulonglong2*)&sB[st][k][cn + 4];
            unsigned long long ar[8] = {aa0.x, aa0.y, aa1.x, aa1.y,
                                        aa2.x, aa2.y, aa3.x, aa3.y};
            unsigned long long br[4] = {bb0.x, bb0.y, bb1.x, bb1.y};
#pragma unroll
            for (int i = 0; i < 8; ++i)
#pragma unroll
                for (int j = 0; j < 4; ++j)
                    asm("fma.rn.f32x2 %0, %1, %2, %3;"
                        : "=l"(acc[i][j])
                        : "l"(ar[i]), "l"(br[j]), "l"(acc[i][j]));
        }

        // store next tile into the other stage (safe: st^1 was consumed
        // before the sync at the top of this iteration)
        if (kt < 15) {
            int ns = st ^ 1;
            sA2[ns][kk + 0][m0] = make_float2(va0.x, va0.x);
            sA2[ns][kk + 1][m0] = make_float2(va0.y, va0.y);
            sA2[ns][kk + 2][m0] = make_float2(va0.z, va0.z);
            sA2[ns][kk + 3][m0] = make_float2(va0.w, va0.w);
            sA2[ns][kk + 0][m1] = make_float2(va1.x, va1.x);
            sA2[ns][kk + 1][m1] = make_float2(va1.y, va1.y);
            sA2[ns][kk + 2][m1] = make_float2(va1.z, va1.z);
            sA2[ns][kk + 3][m1] = make_float2(va1.w, va1.w);
            sB[ns][kk + 0][m0] = vb0.x; sB[ns][kk + 1][m0] = vb0.y;
            sB[ns][kk + 2][m0] = vb0.z; sB[ns][kk + 3][m0] = vb0.w;
            sB[ns][kk + 0][m1] = vb1.x; sB[ns][kk + 1][m1] = vb1.y;
            sB[ns][kk + 2][m1] = vb1.z; sB[ns][kk + 3][m1] = vb1.w;
        }
    }

    // epilogue
#pragma unroll
    for (int i = 0; i < 8; ++i) {
        int gm = row0 + rm + i;
        if (gm >= mlim) continue;
        float* orow = outp + (size_t)gm * ldo + cn;
#pragma unroll
        for (int j = 0; j < 4; ++j) {
            float2 c = *reinterpret_cast<float2*>(&acc[i][j]);
            int cc = 2 * j;
            if (biasp) { c.x += biasp[cn + cc]; c.y += biasp[cn + cc + 1]; }
            if (relu)  { c.x = fmaxf(c.x, 0.f); c.y = fmaxf(c.y, 0.f); }
            *reinterpret_cast<float2*>(orow + cc) = c;
        }
    }
}

// -------- final: out = r + agg2/deg --------
__global__ void final_kernel(float* __restrict__ out) {
    size_t idx = (size_t)blockIdx.x * 256 + threadIdx.x;   // float4 index
    if (idx >= (size_t)NNODES * 32) return;
    int m = (int)(idx >> 5);
    float rdeg = 1.0f / fmaxf(g_deg[m], 1.0f);
    float4 o = ((float4*)out)[idx];
    float4 a = ((const float4*)g_agg2)[idx];
    o.x += a.x * rdeg; o.y += a.y * rdeg;
    o.z += a.z * rdeg; o.w += a.w * rdeg;
    ((float4*)out)[idx] = o;
}

extern "C" void kernel_launch(void* const* d_in, const int* in_sizes, int n_in,
                              void* d_out, int out_size) {
    const float* x   = (const float*)d_in[0];
    const void*  ei  = d_in[1];
    const float* W1l = (const float*)d_in[2];
    const float* b1  = (const float*)d_in[3];
    const float* W1r = (const float*)d_in[4];
    const float* W2l = (const float*)d_in[5];
    const float* b2  = (const float*)d_in[6];
    const float* W2r = (const float*)d_in[7];
    float* out = (float*)d_out;

    detect_kernel<<<1, 256>>>((const int*)ei);
    zero_kernel<<<2048, 256>>>();
    prep_weights<<<256, 256>>>(W1l, W1r, W2l, W2r);

    // layer 1: aggregate x, then fused GEMM -> h = relu([mean||x] @ W1cat^T + b1)
    agg_kernel<<<NEDGES / 8, 256>>>(x, ei, 0);
    build_in1<<<(unsigned)(((size_t)NPAD * 64 + 255) / 256), 256>>>(x);
    gemm256<<<dim3(NBM, 2), 256>>>(1, b1, b2, out);

    // layer 2: GEMM first (p = h@W2l^T, r = h@W2r^T + b2 -> d_out), then aggregate p
    gemm256<<<dim3(NBM, 2), 256>>>(2, b1, b2, out);
    agg_kernel<<<NEDGES / 8, 256>>>(x, ei, 1);
    final_kernel<<<(unsigned)(((size_t)NNODES * 32 + 255) / 256), 256>>>(out);
}

// round 6
// speedup vs baseline: 1.8941x; 1.7090x over previous
#include <cuda_runtime.h>
#include <cuda_bf16.h>
#include <cstdint>
#include <cstddef>

#define NNODES 100000
#define NPAD   100096           // 782 * 128
#define NEDGES 1600000
#define NBM    782              // NPAD / 128

// ---------------- scratch (device globals) ----------------
__device__ __align__(16) float g_agg1[(size_t)NPAD * 128];
__device__ __align__(16) float g_p   [(size_t)NPAD * 128];
__device__ __align__(16) float g_agg2[(size_t)NPAD * 128];
__device__ __align__(16) float g_deg [NPAD];
__device__ __align__(16) __nv_bfloat16 g_ahi[(size_t)NPAD * 256];  // layer1 input hi
__device__ __align__(16) __nv_bfloat16 g_alo[(size_t)NPAD * 256];  // layer1 input lo
__device__ __align__(16) __nv_bfloat16 g_bhi[(size_t)NPAD * 256];  // layer2 input hi
__device__ __align__(16) __nv_bfloat16 g_blo[(size_t)NPAD * 256];  // layer2 input lo
__device__ __align__(16) __nv_bfloat16 g_w1hi[256 * 256];
__device__ __align__(16) __nv_bfloat16 g_w1lo[256 * 256];
__device__ __align__(16) __nv_bfloat16 g_w2hi[256 * 256];
__device__ __align__(16) __nv_bfloat16 g_w2lo[256 * 256];
__device__ int g_is64;

__device__ __forceinline__ uint32_t smem_u32(const void* p) {
    uint32_t a;
    asm("{ .reg .u64 t; cvta.to.shared.u64 t, %1; cvt.u32.u64 %0, t; }"
        : "=r"(a) : "l"(p));
    return a;
}

#define MMA_BF16(c, a, b0, b1) \
    asm volatile("mma.sync.aligned.m16n8k16.row.col.f32.bf16.bf16.f32 " \
        "{%0,%1,%2,%3}, {%4,%5,%6,%7}, {%8,%9}, {%0,%1,%2,%3};" \
        : "+f"((c)[0]), "+f"((c)[1]), "+f"((c)[2]), "+f"((c)[3]) \
        : "r"((a)[0]), "r"((a)[1]), "r"((a)[2]), "r"((a)[3]), "r"(b0), "r"(b1))

#define CP_ASYNC16(dst, src) \
    asm volatile("cp.async.cg.shared.global [%0], [%1], 16;" \
                 :: "r"(dst), "l"(src) : "memory")
#define CP_COMMIT() asm volatile("cp.async.commit_group;" ::: "memory")
#define CP_WAIT0()  asm volatile("cp.async.wait_group 0;" ::: "memory")

// ---------------- small kernels ----------------
__global__ void detect_kernel(const int* __restrict__ ei32) {
    __shared__ int sOr;
    if (threadIdx.x == 0) sOr = 0;
    __syncthreads();
    int acc = 0;
    for (int i = threadIdx.x; i < 2048; i += blockDim.x) acc |= ei32[2 * i + 1];
    atomicOr(&sOr, acc);
    __syncthreads();
    if (threadIdx.x == 0) g_is64 = (sOr == 0) ? 1 : 0;
}

__global__ void zero_kernel() {
    size_t i = (size_t)blockIdx.x * blockDim.x + threadIdx.x;
    size_t stride = (size_t)gridDim.x * blockDim.x;
    float4 z = make_float4(0.f, 0.f, 0.f, 0.f);
    float4* a1 = (float4*)g_agg1;
    float4* a2 = (float4*)g_agg2;
    for (size_t q = i; q < (size_t)NPAD * 32; q += stride) { a1[q] = z; a2[q] = z; }
    for (size_t q = i; q < (size_t)NPAD; q += stride) g_deg[q] = 0.f;
}

__global__ void prep_weights(const float* __restrict__ W1l, const float* __restrict__ W1r,
                             const float* __restrict__ W2l, const float* __restrict__ W2r) {
    int j = blockIdx.x;    // out dim
    int k = threadIdx.x;   // in dim
    float w1 = (k < 128) ? W1l[j * 128 + k] : W1r[j * 128 + (k - 128)];
    float w2 = (j < 128) ? W2l[j * 256 + k] : W2r[(j - 128) * 256 + k];
    __nv_bfloat16 h1 = __float2bfloat16(w1);
    __nv_bfloat16 h2 = __float2bfloat16(w2);
    g_w1hi[j * 256 + k] = h1;
    g_w1lo[j * 256 + k] = __float2bfloat16(w1 - __bfloat162float(h1));
    g_w2hi[j * 256 + k] = h2;
    g_w2lo[j * 256 + k] = __float2bfloat16(w2 - __bfloat162float(h2));
}

__global__ void agg_kernel(const float* __restrict__ xsrc,
                           const void* __restrict__ ei, int phase) {
    int gw = (int)(((size_t)blockIdx.x * blockDim.x + threadIdx.x) >> 5);
    int lane = threadIdx.x & 31;
    if (gw >= NEDGES) return;
    int s, t;
    if (g_is64) {
        const long long* e64 = (const long long*)ei;
        s = (int)e64[gw];
        t = (int)e64[(size_t)NEDGES + gw];
    } else {
        const int* e32 = (const int*)ei;
        s = e32[gw];
        t = e32[(size_t)NEDGES + gw];
    }
    if ((unsigned)s >= NNODES || (unsigned)t >= NNODES) return;
    const float* src = (phase == 0) ? xsrc : g_p;
    float*       dst = (phase == 0) ? g_agg1 : g_agg2;
    float4 v = ((const float4*)(src + ((size_t)s << 7)))[lane];
    float* d = dst + ((size_t)t << 7) + ((size_t)lane << 2);
    asm volatile("red.global.add.v4.f32 [%0], {%1,%2,%3,%4};"
                 :: "l"(d), "f"(v.x), "f"(v.y), "f"(v.z), "f"(v.w) : "memory");
    if (phase == 0 && lane == 0) atomicAdd(g_deg + t, 1.0f);
}

// build [mean || x] directly as bf16 hi/lo into g_ahi/g_alo
__global__ void build_in1(const float* __restrict__ x) {
    size_t idx = (size_t)blockIdx.x * 256 + threadIdx.x;   // float4 index
    if (idx >= (size_t)NPAD * 64) return;
    int m = (int)(idx >> 6);
    int q = (int)(idx & 63);
    float4 v;
    if (q < 32) {
        float rdeg = 1.0f / fmaxf(g_deg[m], 1.0f);
        float4 a = ((const float4*)g_agg1)[(size_t)m * 32 + q];
        v = make_float4(a.x * rdeg, a.y * rdeg, a.z * rdeg, a.w * rdeg);
    } else {
        if (m < NNODES) v = ((const float4*)x)[(size_t)m * 32 + (q - 32)];
        else            v = make_float4(0.f, 0.f, 0.f, 0.f);
    }
    float vv[4] = {v.x, v.y, v.z, v.w};
    __nv_bfloat16 hi[4], lo[4];
#pragma unroll
    for (int j = 0; j < 4; ++j) {
        hi[j] = __float2bfloat16(vv[j]);
        lo[j] = __float2bfloat16(vv[j] - __bfloat162float(hi[j]));
    }
    *(uint2*)(g_ahi + idx * 4) = *(const uint2*)hi;
    *(uint2*)(g_alo + idx * 4) = *(const uint2*)lo;
}

// ---------------- mma.sync GEMM ----------------
// C[128-row tile, 128-col(by) tile] = A[.,256] @ W[.,256]^T, 3-term bf16 split.
// SMEM stage (40960B): Ahi,Alo,Whi,Wlo tiles of 128 rows x 32 bf16, rows padded
// to 80B (conflict-free fragment loads). Two stages, cp.async double buffering.
#define TILE_B   10240      // 128 * 80
#define STAGE_B  40960
#define GEMM_SMEM 81920

__device__ __forceinline__ void cp_stage(uint32_t sb,
    const __nv_bfloat16* Ahi, const __nv_bfloat16* Alo,
    const __nv_bfloat16* Whi, const __nv_bfloat16* Wlo,
    int row0, int nbase, int kt, int st, int tid) {
#pragma unroll
    for (int i = 0; i < 8; ++i) {
        int c = i * 256 + tid;          // 0..2047
        int tile = c >> 9;              // 0:Ahi 1:Alo 2:Whi 3:Wlo
        int idx  = c & 511;
        int row  = idx >> 2;
        int kc   = idx & 3;             // 16B chunk within 64B row
        uint32_t dst = sb + st * STAGE_B + tile * TILE_B
                     + (uint32_t)(row * 80 + kc * 16);
        const __nv_bfloat16* g;
        if (tile == 0)      g = Ahi + (size_t)(row0 + row) * 256;
        else if (tile == 1) g = Alo + (size_t)(row0 + row) * 256;
        else if (tile == 2) g = Whi + (size_t)(nbase + row) * 256;
        else                g = Wlo + (size_t)(nbase + row) * 256;
        g += kt * 32 + kc * 8;
        CP_ASYNC16(dst, g);
    }
}

__global__ void __launch_bounds__(256, 2) gemm_mma(int layer,
                                                   const float* __restrict__ b1v,
                                                   const float* __restrict__ b2v,
                                                   float* __restrict__ dout) {
    extern __shared__ char dsm[];
    int tid = threadIdx.x, lane = tid & 31, wid = tid >> 5;
    int row0 = blockIdx.x * 128;
    int by   = blockIdx.y;
    int nbase = by * 128;

    const __nv_bfloat16* Ahi = (layer == 1) ? g_ahi : g_bhi;
    const __nv_bfloat16* Alo = (layer == 1) ? g_alo : g_blo;
    const __nv_bfloat16* Whi = (layer == 1) ? g_w1hi : g_w2hi;
    const __nv_bfloat16* Wlo = (layer == 1) ? g_w1lo : g_w2lo;

    uint32_t sb = smem_u32(dsm);
    int mrow = (wid >> 1) * 32;     // warp M offset (0..96)
    int ncol = (wid & 1) * 64;      // warp N offset (0 or 64)

    float acc[2][8][4];
#pragma unroll
    for (int mt = 0; mt < 2; ++mt)
#pragma unroll
        for (int j = 0; j < 8; ++j)
#pragma unroll
            for (int q = 0; q < 4; ++q) acc[mt][j][q] = 0.f;

    cp_stage(sb, Ahi, Alo, Whi, Wlo, row0, nbase, 0, 0, tid);
    CP_COMMIT();

    for (int kt = 0; kt < 8; ++kt) {
        int st = kt & 1;
        CP_WAIT0();
        __syncthreads();
        if (kt < 7) {
            cp_stage(sb, Ahi, Alo, Whi, Wlo, row0, nbase, kt + 1, st ^ 1, tid);
            CP_COMMIT();
        }
        const char* sa = dsm + st * STAGE_B;
#pragma unroll
        for (int ks = 0; ks < 2; ++ks) {
            uint32_t a_base = (uint32_t)((mrow + (lane >> 2)) * 80
                                         + (lane & 3) * 4 + ks * 32);
            uint32_t ah[2][4], al[2][4];
#pragma unroll
            for (int mt = 0; mt < 2; ++mt) {
                uint32_t o = a_base + mt * 1280;
                ah[mt][0] = *(const uint32_t*)(sa + o);
                ah[mt][1] = *(const uint32_t*)(sa + o + 640);
                ah[mt][2] = *(const uint32_t*)(sa + o + 16);
                ah[mt][3] = *(const uint32_t*)(sa + o + 656);
                al[mt][0] = *(const uint32_t*)(sa + TILE_B + o);
                al[mt][1] = *(const uint32_t*)(sa + TILE_B + o + 640);
                al[mt][2] = *(const uint32_t*)(sa + TILE_B + o + 16);
                al[mt][3] = *(const uint32_t*)(sa + TILE_B + o + 656);
            }
            uint32_t b_base = (uint32_t)((ncol + (lane >> 2)) * 80
                                         + (lane & 3) * 4 + ks * 32);
#pragma unroll
            for (int j = 0; j < 8; ++j) {
                uint32_t o = b_base + j * 640;
                uint32_t bh0 = *(const uint32_t*)(sa + 2 * TILE_B + o);
                uint32_t bh1 = *(const uint32_t*)(sa + 2 * TILE_B + o + 16);
                uint32_t bl0 = *(const uint32_t*)(sa + 3 * TILE_B + o);
                uint32_t bl1 = *(const uint32_t*)(sa + 3 * TILE_B + o + 16);
#pragma unroll
                for (int mt = 0; mt < 2; ++mt) {
                    MMA_BF16(acc[mt][j], ah[mt], bh0, bh1);
                    MMA_BF16(acc[mt][j], al[mt], bh0, bh1);
                    MMA_BF16(acc[mt][j], ah[mt], bl0, bl1);
                }
            }
        }
        __syncthreads();
    }

    // ---- epilogue ----
    int r_base  = row0 + mrow + (lane >> 2);
    int cl_base = ncol + (lane & 3) * 2;
    if (layer == 1) {
        // h = relu(acc + b1)  -> split hi/lo into g_bhi/g_blo (layer2 input)
#pragma unroll
        for (int mt = 0; mt < 2; ++mt)
#pragma unroll
            for (int j = 0; j < 8; ++j) {
                int gn = nbase + cl_base + j * 8;
                float bx0 = b1v[gn], bx1 = b1v[gn + 1];
#pragma unroll
                for (int hh = 0; hh < 2; ++hh) {
                    int r = r_base + mt * 16 + hh * 8;
                    float v0 = fmaxf(acc[mt][j][hh * 2]     + bx0, 0.f);
                    float v1 = fmaxf(acc[mt][j][hh * 2 + 1] + bx1, 0.f);
                    __nv_bfloat16 h0 = __float2bfloat16(v0);
                    __nv_bfloat16 h1 = __float2bfloat16(v1);
                    __nv_bfloat16 l0 = __float2bfloat16(v0 - __bfloat162float(h0));
                    __nv_bfloat16 l1 = __float2bfloat16(v1 - __bfloat162float(h1));
                    __nv_bfloat16 hp[2] = {h0, h1};
                    __nv_bfloat16 lp[2] = {l0, l1};
                    *(uint32_t*)(g_bhi + (size_t)r * 256 + gn) = *(const uint32_t*)hp;
                    *(uint32_t*)(g_blo + (size_t)r * 256 + gn) = *(const uint32_t*)lp;
                }
            }
    } else {
#pragma unroll
        for (int mt = 0; mt < 2; ++mt)
#pragma unroll
            for (int j = 0; j < 8; ++j) {
                int cl = cl_base + j * 8;
#pragma unroll
                for (int hh = 0; hh < 2; ++hh) {
                    int r = r_base + mt * 16 + hh * 8;
                    float v0 = acc[mt][j][hh * 2];
                    float v1 = acc[mt][j][hh * 2 + 1];
                    if (by == 0) {
                        float2 w = make_float2(v0, v1);
                        *(float2*)(g_p + (size_t)r * 128 + cl) = w;
                    } else if (r < NNODES) {
                        float2 w = make_float2(v0 + b2v[cl], v1 + b2v[cl + 1]);
                        *(float2*)(dout + (size_t)r * 128 + cl) = w;
                    }
                }
            }
    }
}

__global__ void final_kernel(float* __restrict__ out) {
    size_t idx = (size_t)blockIdx.x * 256 + threadIdx.x;
    if (idx >= (size_t)NNODES * 32) return;
    int m = (int)(idx >> 5);
    float rdeg = 1.0f / fmaxf(g_deg[m], 1.0f);
    float4 o = ((float4*)out)[idx];
    float4 a = ((const float4*)g_agg2)[idx];
    o.x += a.x * rdeg; o.y += a.y * rdeg;
    o.z += a.z * rdeg; o.w += a.w * rdeg;
    ((float4*)out)[idx] = o;
}

extern "C" void kernel_launch(void* const* d_in, const int* in_sizes, int n_in,
                              void* d_out, int out_size) {
    const float* x   = (const float*)d_in[0];
    const void*  ei  = d_in[1];
    const float* W1l = (const float*)d_in[2];
    const float* b1  = (const float*)d_in[3];
    const float* W1r = (const float*)d_in[4];
    const float* W2l = (const float*)d_in[5];
    const float* b2  = (const float*)d_in[6];
    const float* W2r = (const float*)d_in[7];
    float* out = (float*)d_out;

    cudaFuncSetAttribute(gemm_mma, cudaFuncAttributeMaxDynamicSharedMemorySize,
                         GEMM_SMEM);

    detect_kernel<<<1, 256>>>((const int*)ei);
    zero_kernel<<<2048, 256>>>();
    prep_weights<<<256, 256>>>(W1l, W1r, W2l, W2r);

    // layer 1: aggregate, build [mean||x] (hi/lo), GEMM -> g_bhi/g_blo
    agg_kernel<<<NEDGES / 8, 256>>>(x, ei, 0);
    build_in1<<<(unsigned)(((size_t)NPAD * 64 + 255) / 256), 256>>>(x);
    gemm_mma<<<dim3(NBM, 2), 256, GEMM_SMEM>>>(1, b1, b2, out);

    // layer 2: GEMM (p and r), aggregate p, finalize
    gemm_mma<<<dim3(NBM, 2), 256, GEMM_SMEM>>>(2, b1, b2, out);
    agg_kernel<<<NEDGES / 8, 256>>>(x, ei, 1);
    final_kernel<<<(unsigned)(((size_t)NNODES * 32 + 255) / 256), 256>>>(out);
}

// round 7
// speedup vs baseline: 2.5262x; 1.3337x over previous
#include <cuda_runtime.h>
#include <cuda_bf16.h>
#include <cstdint>
#include <cstddef>

#define NNODES 100000
#define NPAD   100096           // 782 * 128
#define NEDGES 1600000
#define NBM    782              // NPAD / 128

// ---------------- scratch (device globals) ----------------
__device__ __align__(16) float g_p   [(size_t)NPAD * 128];
__device__ __align__(16) __nv_bfloat16 g_ahi[(size_t)NPAD * 256];  // layer1 input hi
__device__ __align__(16) __nv_bfloat16 g_alo[(size_t)NPAD * 256];  // layer1 input lo
__device__ __align__(16) __nv_bfloat16 g_bhi[(size_t)NPAD * 256];  // layer2 input hi
__device__ __align__(16) __nv_bfloat16 g_blo[(size_t)NPAD * 256];  // layer2 input lo
__device__ __align__(16) __nv_bfloat16 g_w1hi[256 * 256];
__device__ __align__(16) __nv_bfloat16 g_w1lo[256 * 256];
__device__ __align__(16) __nv_bfloat16 g_w2hi[256 * 256];
__device__ __align__(16) __nv_bfloat16 g_w2lo[256 * 256];
__device__ int g_rowptr[NNODES + 1];
__device__ int g_wix[NNODES];
__device__ int g_srcidx[NEDGES];
__device__ int g_is64;

__device__ __forceinline__ uint32_t smem_u32(const void* p) {
    uint32_t a;
    asm("{ .reg .u64 t; cvta.to.shared.u64 t, %1; cvt.u32.u64 %0, t; }"
        : "=r"(a) : "l"(p));
    return a;
}

#define MMA_BF16(c, a, b0, b1) \
    asm volatile("mma.sync.aligned.m16n8k16.row.col.f32.bf16.bf16.f32 " \
        "{%0,%1,%2,%3}, {%4,%5,%6,%7}, {%8,%9}, {%0,%1,%2,%3};" \
        : "+f"((c)[0]), "+f"((c)[1]), "+f"((c)[2]), "+f"((c)[3]) \
        : "r"((a)[0]), "r"((a)[1]), "r"((a)[2]), "r"((a)[3]), "r"(b0), "r"(b1))

#define CP_ASYNC16(dst, src) \
    asm volatile("cp.async.cg.shared.global [%0], [%1], 16;" \
                 :: "r"(dst), "l"(src) : "memory")
#define CP_COMMIT() asm volatile("cp.async.commit_group;" ::: "memory")
#define CP_WAIT0()  asm volatile("cp.async.wait_group 0;" ::: "memory")

// ---------------- edge index decode ----------------
__device__ __forceinline__ void load_edge(const void* ei, int e, int& s, int& t) {
    if (g_is64) {
        const long long* e64 = (const long long*)ei;
        s = (int)e64[e];
        t = (int)e64[(size_t)NEDGES + e];
    } else {
        const int* e32 = (const int*)ei;
        s = e32[e];
        t = e32[(size_t)NEDGES + e];
    }
}

__global__ void detect_kernel(const int* __restrict__ ei32) {
    __shared__ int sOr;
    if (threadIdx.x == 0) sOr = 0;
    __syncthreads();
    int acc = 0;
    for (int i = threadIdx.x; i < 2048; i += blockDim.x) acc |= ei32[2 * i + 1];
    atomicOr(&sOr, acc);
    __syncthreads();
    if (threadIdx.x == 0) g_is64 = (sOr == 0) ? 1 : 0;
}

// ---------------- CSR build (by target) ----------------
__global__ void zero_wix() {
    int i = blockIdx.x * blockDim.x + threadIdx.x;
    if (i < NNODES) g_wix[i] = 0;
}

__global__ void count_kernel(const void* __restrict__ ei) {
    int e = blockIdx.x * blockDim.x + threadIdx.x;
    if (e >= NEDGES) return;
    int s, t;
    load_edge(ei, e, s, t);
    if ((unsigned)s >= NNODES || (unsigned)t >= NNODES) return;
    atomicAdd(&g_wix[t], 1);
}

// single-block scan: 1024 threads, 98 nodes each
__global__ void scan_kernel() {
    __shared__ int sums[1024];
    int tid = threadIdx.x;
    int base = tid * 98;
    int acc = 0;
    for (int i = 0; i < 98; ++i) {
        int idx = base + i;
        if (idx < NNODES) acc += g_wix[idx];
    }
    sums[tid] = acc;
    __syncthreads();
    for (int off = 1; off < 1024; off <<= 1) {
        int v = 0;
        if (tid >= off) v = sums[tid - off];
        __syncthreads();
        if (tid >= off) sums[tid] += v;
        __syncthreads();
    }
    int run = (tid == 0) ? 0 : sums[tid - 1];
    for (int i = 0; i < 98; ++i) {
        int idx = base + i;
        if (idx < NNODES) {
            int c = g_wix[idx];
            g_rowptr[idx] = run;
            g_wix[idx] = run;   // becomes the write cursor
            run += c;
        }
    }
    if (tid == 1023) g_rowptr[NNODES] = run;
}

__global__ void scatter_kernel(const void* __restrict__ ei) {
    int e = blockIdx.x * blockDim.x + threadIdx.x;
    if (e >= NEDGES) return;
    int s, t;
    load_edge(ei, e, s, t);
    if ((unsigned)s >= NNODES || (unsigned)t >= NNODES) return;
    int pos = atomicAdd(&g_wix[t], 1);
    g_srcidx[pos] = s;
}

// ---------------- gather aggregation: one warp per node ----------------
// phase 0: mean of x rows -> bf16 hi/lo into g_ahi/g_alo cols [0,128)
// phase 1: mean of g_p rows -> out[node] += mean
__global__ void gather_kernel(const float* __restrict__ x,
                              float* __restrict__ out, int phase) {
    int node = (int)(((size_t)blockIdx.x * blockDim.x + threadIdx.x) >> 5);
    int lane = threadIdx.x & 31;
    if (node >= NNODES) return;
    int beg = g_rowptr[node];
    int end = g_rowptr[node + 1];
    const float* src = (phase == 0) ? x : g_p;

    float4 acc = make_float4(0.f, 0.f, 0.f, 0.f);
    int i = beg;
    for (; i + 3 < end; i += 4) {
        int s0 = g_srcidx[i], s1 = g_srcidx[i + 1];
        int s2 = g_srcidx[i + 2], s3 = g_srcidx[i + 3];
        float4 v0 = ((const float4*)(src + ((size_t)s0 << 7)))[lane];
        float4 v1 = ((const float4*)(src + ((size_t)s1 << 7)))[lane];
        float4 v2 = ((const float4*)(src + ((size_t)s2 << 7)))[lane];
        float4 v3 = ((const float4*)(src + ((size_t)s3 << 7)))[lane];
        acc.x += v0.x + v1.x + v2.x + v3.x;
        acc.y += v0.y + v1.y + v2.y + v3.y;
        acc.z += v0.z + v1.z + v2.z + v3.z;
        acc.w += v0.w + v1.w + v2.w + v3.w;
    }
    for (; i < end; ++i) {
        int s0 = g_srcidx[i];
        float4 v0 = ((const float4*)(src + ((size_t)s0 << 7)))[lane];
        acc.x += v0.x; acc.y += v0.y; acc.z += v0.z; acc.w += v0.w;
    }
    float rdeg = 1.0f / fmaxf((float)(end - beg), 1.0f);
    float vv[4] = {acc.x * rdeg, acc.y * rdeg, acc.z * rdeg, acc.w * rdeg};

    if (phase == 0) {
        __nv_bfloat16 hi[4], lo[4];
#pragma unroll
        for (int j = 0; j < 4; ++j) {
            hi[j] = __float2bfloat16(vv[j]);
            lo[j] = __float2bfloat16(vv[j] - __bfloat162float(hi[j]));
        }
        *(uint2*)(g_ahi + (size_t)node * 256 + lane * 4) = *(const uint2*)hi;
        *(uint2*)(g_alo + (size_t)node * 256 + lane * 4) = *(const uint2*)lo;
    } else {
        float4* op = (float4*)out + (size_t)node * 32 + lane;
        float4 o = *op;
        o.x += vv[0]; o.y += vv[1]; o.z += vv[2]; o.w += vv[3];
        *op = o;
    }
}

// x part (cols 128..255) as hi/lo; zero pad rows entirely
__global__ void xsplit_kernel(const float* __restrict__ x) {
    size_t idx = (size_t)blockIdx.x * 256 + threadIdx.x;   // float4 index
    if (idx >= (size_t)NPAD * 32) return;
    int m = (int)(idx >> 5);
    int q = (int)(idx & 31);
    float4 v = make_float4(0.f, 0.f, 0.f, 0.f);
    if (m < NNODES) v = ((const float4*)x)[(size_t)m * 32 + q];
    float vv[4] = {v.x, v.y, v.z, v.w};
    __nv_bfloat16 hi[4], lo[4];
#pragma unroll
    for (int j = 0; j < 4; ++j) {
        hi[j] = __float2bfloat16(vv[j]);
        lo[j] = __float2bfloat16(vv[j] - __bfloat162float(hi[j]));
    }
    *(uint2*)(g_ahi + (size_t)m * 256 + 128 + q * 4) = *(const uint2*)hi;
    *(uint2*)(g_alo + (size_t)m * 256 + 128 + q * 4) = *(const uint2*)lo;
    if (m >= NNODES) {   // zero the mean half of pad rows
        uint2 z = make_uint2(0u, 0u);
        *(uint2*)(g_ahi + (size_t)m * 256 + q * 4) = z;
        *(uint2*)(g_alo + (size_t)m * 256 + q * 4) = z;
    }
}

__global__ void prep_weights(const float* __restrict__ W1l, const float* __restrict__ W1r,
                             const float* __restrict__ W2l, const float* __restrict__ W2r) {
    int j = blockIdx.x;    // out dim
    int k = threadIdx.x;   // in dim
    float w1 = (k < 128) ? W1l[j * 128 + k] : W1r[j * 128 + (k - 128)];
    float w2 = (j < 128) ? W2l[j * 256 + k] : W2r[(j - 128) * 256 + k];
    __nv_bfloat16 h1 = __float2bfloat16(w1);
    __nv_bfloat16 h2 = __float2bfloat16(w2);
    g_w1hi[j * 256 + k] = h1;
    g_w1lo[j * 256 + k] = __float2bfloat16(w1 - __bfloat162float(h1));
    g_w2hi[j * 256 + k] = h2;
    g_w2lo[j * 256 + k] = __float2bfloat16(w2 - __bfloat162float(h2));
}

// ---------------- mma.sync GEMM (same as R6) ----------------
#define TILE_B   10240      // 128 * 80
#define STAGE_B  40960
#define GEMM_SMEM 81920

__device__ __forceinline__ void cp_stage(uint32_t sb,
    const __nv_bfloat16* Ahi, const __nv_bfloat16* Alo,
    const __nv_bfloat16* Whi, const __nv_bfloat16* Wlo,
    int row0, int nbase, int kt, int st, int tid) {
#pragma unroll
    for (int i = 0; i < 8; ++i) {
        int c = i * 256 + tid;          // 0..2047
        int tile = c >> 9;              // 0:Ahi 1:Alo 2:Whi 3:Wlo
        int idx  = c & 511;
        int row  = idx >> 2;
        int kc   = idx & 3;
        uint32_t dst = sb + st * STAGE_B + tile * TILE_B
                     + (uint32_t)(row * 80 + kc * 16);
        const __nv_bfloat16* g;
        if (tile == 0)      g = Ahi + (size_t)(row0 + row) * 256;
        else if (tile == 1) g = Alo + (size_t)(row0 + row) * 256;
        else if (tile == 2) g = Whi + (size_t)(nbase + row) * 256;
        else                g = Wlo + (size_t)(nbase + row) * 256;
        g += kt * 32 + kc * 8;
        CP_ASYNC16(dst, g);
    }
}

__global__ void __launch_bounds__(256, 2) gemm_mma(int layer,
                                                   const float* __restrict__ b1v,
                                                   const float* __restrict__ b2v,
                                                   float* __restrict__ dout) {
    extern __shared__ char dsm[];
    int tid = threadIdx.x, lane = tid & 31, wid = tid >> 5;
    int row0 = blockIdx.x * 128;
    int by   = blockIdx.y;
    int nbase = by * 128;

    const __nv_bfloat16* Ahi = (layer == 1) ? g_ahi : g_bhi;
    const __nv_bfloat16* Alo = (layer == 1) ? g_alo : g_blo;
    const __nv_bfloat16* Whi = (layer == 1) ? g_w1hi : g_w2hi;
    const __nv_bfloat16* Wlo = (layer == 1) ? g_w1lo : g_w2lo;

    uint32_t sb = smem_u32(dsm);
    int mrow = (wid >> 1) * 32;
    int ncol = (wid & 1) * 64;

    float acc[2][8][4];
#pragma unroll
    for (int mt = 0; mt < 2; ++mt)
#pragma unroll
        for (int j = 0; j < 8; ++j)
#pragma unroll
            for (int q = 0; q < 4; ++q) acc[mt][j][q] = 0.f;

    cp_stage(sb, Ahi, Alo, Whi, Wlo, row0, nbase, 0, 0, tid);
    CP_COMMIT();

    for (int kt = 0; kt < 8; ++kt) {
        int st = kt & 1;
        CP_WAIT0();
        __syncthreads();
        if (kt < 7) {
            cp_stage(sb, Ahi, Alo, Whi, Wlo, row0, nbase, kt + 1, st ^ 1, tid);
            CP_COMMIT();
        }
        const char* sa = dsm + st * STAGE_B;
#pragma unroll
        for (int ks = 0; ks < 2; ++ks) {
            uint32_t a_base = (uint32_t)((mrow + (lane >> 2)) * 80
                                         + (lane & 3) * 4 + ks * 32);
            uint32_t ah[2][4], al[2][4];
#pragma unroll
            for (int mt = 0; mt < 2; ++mt) {
                uint32_t o = a_base + mt * 1280;
                ah[mt][0] = *(const uint32_t*)(sa + o);
                ah[mt][1] = *(const uint32_t*)(sa + o + 640);
                ah[mt][2] = *(const uint32_t*)(sa + o + 16);
                ah[mt][3] = *(const uint32_t*)(sa + o + 656);
                al[mt][0] = *(const uint32_t*)(sa + TILE_B + o);
                al[mt][1] = *(const uint32_t*)(sa + TILE_B + o + 640);
                al[mt][2] = *(const uint32_t*)(sa + TILE_B + o + 16);
                al[mt][3] = *(const uint32_t*)(sa + TILE_B + o + 656);
            }
            uint32_t b_base = (uint32_t)((ncol + (lane >> 2)) * 80
                                         + (lane & 3) * 4 + ks * 32);
#pragma unroll
            for (int j = 0; j < 8; ++j) {
                uint32_t o = b_base + j * 640;
                uint32_t bh0 = *(const uint32_t*)(sa + 2 * TILE_B + o);
                uint32_t bh1 = *(const uint32_t*)(sa + 2 * TILE_B + o + 16);
                uint32_t bl0 = *(const uint32_t*)(sa + 3 * TILE_B + o);
                uint32_t bl1 = *(const uint32_t*)(sa + 3 * TILE_B + o + 16);
#pragma unroll
                for (int mt = 0; mt < 2; ++mt) {
                    MMA_BF16(acc[mt][j], ah[mt], bh0, bh1);
                    MMA_BF16(acc[mt][j], al[mt], bh0, bh1);
                    MMA_BF16(acc[mt][j], ah[mt], bl0, bl1);
                }
            }
        }
        __syncthreads();
    }

    int r_base  = row0 + mrow + (lane >> 2);
    int cl_base = ncol + (lane & 3) * 2;
    if (layer == 1) {
#pragma unroll
        for (int mt = 0; mt < 2; ++mt)
#pragma unroll
            for (int j = 0; j < 8; ++j) {
                int gn = nbase + cl_base + j * 8;
                float bx0 = b1v[gn], bx1 = b1v[gn + 1];
#pragma unroll
                for (int hh = 0; hh < 2; ++hh) {
                    int r = r_base + mt * 16 + hh * 8;
                    float v0 = fmaxf(acc[mt][j][hh * 2]     + bx0, 0.f);
                    float v1 = fmaxf(acc[mt][j][hh * 2 + 1] + bx1, 0.f);
                    __nv_bfloat16 h0 = __float2bfloat16(v0);
                    __nv_bfloat16 h1 = __float2bfloat16(v1);
                    __nv_bfloat16 l0 = __float2bfloat16(v0 - __bfloat162float(h0));
                    __nv_bfloat16 l1 = __float2bfloat16(v1 - __bfloat162float(h1));
                    __nv_bfloat16 hp[2] = {h0, h1};
                    __nv_bfloat16 lp[2] = {l0, l1};
                    *(uint32_t*)(g_bhi + (size_t)r * 256 + gn) = *(const uint32_t*)hp;
                    *(uint32_t*)(g_blo + (size_t)r * 256 + gn) = *(const uint32_t*)lp;
                }
            }
    } else {
#pragma unroll
        for (int mt = 0; mt < 2; ++mt)
#pragma unroll
            for (int j = 0; j < 8; ++j) {
                int cl = cl_base + j * 8;
#pragma unroll
                for (int hh = 0; hh < 2; ++hh) {
                    int r = r_base + mt * 16 + hh * 8;
                    float v0 = acc[mt][j][hh * 2];
                    float v1 = acc[mt][j][hh * 2 + 1];
                    if (by == 0) {
                        float2 w = make_float2(v0, v1);
                        *(float2*)(g_p + (size_t)r * 128 + cl) = w;
                    } else if (r < NNODES) {
                        float2 w = make_float2(v0 + b2v[cl], v1 + b2v[cl + 1]);
                        *(float2*)(dout + (size_t)r * 128 + cl) = w;
                    }
                }
            }
    }
}

extern "C" void kernel_launch(void* const* d_in, const int* in_sizes, int n_in,
                              void* d_out, int out_size) {
    const float* x   = (const float*)d_in[0];
    const void*  ei  = d_in[1];
    const float* W1l = (const float*)d_in[2];
    const float* b1  = (const float*)d_in[3];
    const float* W1r = (const float*)d_in[4];
    const float* W2l = (const float*)d_in[5];
    const float* b2  = (const float*)d_in[6];
    const float* W2r = (const float*)d_in[7];
    float* out = (float*)d_out;

    cudaFuncSetAttribute(gemm_mma, cudaFuncAttributeMaxDynamicSharedMemorySize,
                         GEMM_SMEM);

    // CSR build (once) + weight prep
    detect_kernel<<<1, 256>>>((const int*)ei);
    zero_wix<<<(NNODES + 255) / 256, 256>>>();
    count_kernel<<<(NEDGES + 255) / 256, 256>>>(ei);
    scan_kernel<<<1, 1024>>>();
    scatter_kernel<<<(NEDGES + 255) / 256, 256>>>(ei);
    prep_weights<<<256, 256>>>(W1l, W1r, W2l, W2r);

    // layer 1: gather-mean(x) -> g_ahi/alo[:,0:128); x -> cols [128,256)
    gather_kernel<<<12500, 256>>>(x, out, 0);
    xsplit_kernel<<<(unsigned)(((size_t)NPAD * 32 + 255) / 256), 256>>>(x);
    gemm_mma<<<dim3(NBM, 2), 256, GEMM_SMEM>>>(1, b1, b2, out);

    // layer 2: GEMM (p -> g_p, r + b2 -> out), then out += gather-mean(p)
    gemm_mma<<<dim3(NBM, 2), 256, GEMM_SMEM>>>(2, b1, b2, out);
    gather_kernel<<<12500, 256>>>(x, out, 1);
}

// round 8
// speedup vs baseline: 3.2990x; 1.3060x over previous
#include <cuda_runtime.h>
#include <cuda_bf16.h>
#include <cstdint>
#include <cstddef>

#define NNODES 100000
#define NPAD   100096           // 782 * 128
#define NEDGES 1600000
#define NBM    782              // NPAD / 128
#define SCAN_BLOCKS 98          // 98 * 1024 >= NNODES

// ---------------- scratch (device globals) ----------------
__device__ __align__(16) float g_p   [(size_t)NPAD * 128];
__device__ __align__(16) __nv_bfloat16 g_ahi[(size_t)NPAD * 256];  // layer1 input hi
__device__ __align__(16) __nv_bfloat16 g_alo[(size_t)NPAD * 256];  // layer1 input lo
__device__ __align__(16) __nv_bfloat16 g_bhi[(size_t)NPAD * 256];  // layer2 input hi
__device__ __align__(16) __nv_bfloat16 g_blo[(size_t)NPAD * 256];  // layer2 input lo
__device__ __align__(16) __nv_bfloat16 g_w1hi[256 * 256];
__device__ __align__(16) __nv_bfloat16 g_w1lo[256 * 256];
__device__ __align__(16) __nv_bfloat16 g_w2hi[256 * 256];
__device__ __align__(16) __nv_bfloat16 g_w2lo[256 * 256];
__device__ int g_rowptr[NNODES + 1];
__device__ int g_wix[NNODES];
__device__ int g_srcidx[NEDGES];
__device__ int g_bsum[SCAN_BLOCKS];
__device__ int g_boff[SCAN_BLOCKS];
__device__ int g_is64;

__device__ __forceinline__ uint32_t smem_u32(const void* p) {
    uint32_t a;
    asm("{ .reg .u64 t; cvta.to.shared.u64 t, %1; cvt.u32.u64 %0, t; }"
        : "=r"(a) : "l"(p));
    return a;
}

#define MMA_BF16(c, a, b0, b1) \
    asm volatile("mma.sync.aligned.m16n8k16.row.col.f32.bf16.bf16.f32 " \
        "{%0,%1,%2,%3}, {%4,%5,%6,%7}, {%8,%9}, {%0,%1,%2,%3};" \
        : "+f"((c)[0]), "+f"((c)[1]), "+f"((c)[2]), "+f"((c)[3]) \
        : "r"((a)[0]), "r"((a)[1]), "r"((a)[2]), "r"((a)[3]), "r"(b0), "r"(b1))

#define CP_ASYNC16(dst, src) \
    asm volatile("cp.async.cg.shared.global [%0], [%1], 16;" \
                 :: "r"(dst), "l"(src) : "memory")
#define CP_COMMIT() asm volatile("cp.async.commit_group;" ::: "memory")
#define CP_WAIT0()  asm volatile("cp.async.wait_group 0;" ::: "memory")

// ---------------- edge index decode ----------------
__device__ __forceinline__ void load_edge(const void* ei, int e, int& s, int& t) {
    if (g_is64) {
        const long long* e64 = (const long long*)ei;
        s = (int)e64[e];
        t = (int)e64[(size_t)NEDGES + e];
    } else {
        const int* e32 = (const int*)ei;
        s = e32[e];
        t = e32[(size_t)NEDGES + e];
    }
}

__global__ void detect_kernel(const int* __restrict__ ei32) {
    __shared__ int sOr;
    if (threadIdx.x == 0) sOr = 0;
    __syncthreads();
    int acc = 0;
    for (int i = threadIdx.x; i < 2048; i += blockDim.x) acc |= ei32[2 * i + 1];
    atomicOr(&sOr, acc);
    __syncthreads();
    if (threadIdx.x == 0) g_is64 = (sOr == 0) ? 1 : 0;
}

// ---------------- CSR build (by target) ----------------
__global__ void zero_wix() {
    int i = blockIdx.x * blockDim.x + threadIdx.x;
    if (i < NNODES) g_wix[i] = 0;
}

__global__ void count_kernel(const void* __restrict__ ei) {
    int e = blockIdx.x * blockDim.x + threadIdx.x;
    if (e >= NEDGES) return;
    int s, t;
    load_edge(ei, e, s, t);
    if ((unsigned)s >= NNODES || (unsigned)t >= NNODES) return;
    atomicAdd(&g_wix[t], 1);
}

// stage 1: per-block (1024 nodes) sum of counts
__global__ void blocksum_kernel() {
    __shared__ int red[32];
    int idx = blockIdx.x * 1024 + threadIdx.x;
    int v = (idx < NNODES) ? g_wix[idx] : 0;
#pragma unroll
    for (int o = 16; o > 0; o >>= 1) v += __shfl_down_sync(0xFFFFFFFFu, v, o);
    if ((threadIdx.x & 31) == 0) red[threadIdx.x >> 5] = v;
    __syncthreads();
    if (threadIdx.x < 32) {
        int w = red[threadIdx.x];
#pragma unroll
        for (int o = 16; o > 0; o >>= 1) w += __shfl_down_sync(0xFFFFFFFFu, w, o);
        if (threadIdx.x == 0) g_bsum[blockIdx.x] = w;
    }
}

// stage 2: exclusive scan of SCAN_BLOCKS block sums (one small block)
__global__ void scan_bsum() {
    __shared__ int s[SCAN_BLOCKS];
    int tid = threadIdx.x;
    if (tid < SCAN_BLOCKS) s[tid] = g_bsum[tid];
    __syncthreads();
    if (tid == 0) {
        int run = 0;
        for (int i = 0; i < SCAN_BLOCKS; ++i) {
            g_boff[i] = run;
            run += s[i];
        }
        g_rowptr[NNODES] = run;
    }
}

// stage 3: in-block exclusive scan + block offset -> rowptr, wix(cursor)
__global__ void rowptr_kernel() {
    __shared__ int sc[1024];
    int tid = threadIdx.x;
    int idx = blockIdx.x * 1024 + tid;
    int v = (idx < NNODES) ? g_wix[idx] : 0;
    sc[tid] = v;
    __syncthreads();
#pragma unroll
    for (int off = 1; off < 1024; off <<= 1) {
        int u = (tid >= off) ? sc[tid - off] : 0;
        __syncthreads();
        sc[tid] += u;
        __syncthreads();
    }
    if (idx < NNODES) {
        int excl = sc[tid] - v + g_boff[blockIdx.x];
        g_rowptr[idx] = excl;
        g_wix[idx] = excl;
    }
}

__global__ void scatter_kernel(const void* __restrict__ ei) {
    int e = blockIdx.x * blockDim.x + threadIdx.x;
    if (e >= NEDGES) return;
    int s, t;
    load_edge(ei, e, s, t);
    if ((unsigned)s >= NNODES || (unsigned)t >= NNODES) return;
    int pos = atomicAdd(&g_wix[t], 1);
    g_srcidx[pos] = s;
}

// ---------------- gather aggregation: one warp per node ----------------
__global__ void gather_kernel(const float* __restrict__ x,
                              float* __restrict__ out, int phase) {
    int node = (int)(((size_t)blockIdx.x * blockDim.x + threadIdx.x) >> 5);
    int lane = threadIdx.x & 31;
    if (node >= NNODES) return;
    int beg = g_rowptr[node];
    int end = g_rowptr[node + 1];
    const float* src = (phase == 0) ? x : g_p;

    float4 acc = make_float4(0.f, 0.f, 0.f, 0.f);
    int i = beg;
    for (; i + 3 < end; i += 4) {
        int s0 = g_srcidx[i], s1 = g_srcidx[i + 1];
        int s2 = g_srcidx[i + 2], s3 = g_srcidx[i + 3];
        float4 v0 = ((const float4*)(src + ((size_t)s0 << 7)))[lane];
        float4 v1 = ((const float4*)(src + ((size_t)s1 << 7)))[lane];
        float4 v2 = ((const float4*)(src + ((size_t)s2 << 7)))[lane];
        float4 v3 = ((const float4*)(src + ((size_t)s3 << 7)))[lane];
        acc.x += v0.x + v1.x + v2.x + v3.x;
        acc.y += v0.y + v1.y + v2.y + v3.y;
        acc.z += v0.z + v1.z + v2.z + v3.z;
        acc.w += v0.w + v1.w + v2.w + v3.w;
    }
    for (; i < end; ++i) {
        int s0 = g_srcidx[i];
        float4 v0 = ((const float4*)(src + ((size_t)s0 << 7)))[lane];
        acc.x += v0.x; acc.y += v0.y; acc.z += v0.z; acc.w += v0.w;
    }
    float rdeg = 1.0f / fmaxf((float)(end - beg), 1.0f);
    float vv[4] = {acc.x * rdeg, acc.y * rdeg, acc.z * rdeg, acc.w * rdeg};

    if (phase == 0) {
        __nv_bfloat16 hi[4], lo[4];
#pragma unroll
        for (int j = 0; j < 4; ++j) {
            hi[j] = __float2bfloat16(vv[j]);
            lo[j] = __float2bfloat16(vv[j] - __bfloat162float(hi[j]));
        }
        *(uint2*)(g_ahi + (size_t)node * 256 + lane * 4) = *(const uint2*)hi;
        *(uint2*)(g_alo + (size_t)node * 256 + lane * 4) = *(const uint2*)lo;
    } else {
        float4* op = (float4*)out + (size_t)node * 32 + lane;
        float4 o = *op;
        o.x += vv[0]; o.y += vv[1]; o.z += vv[2]; o.w += vv[3];
        *op = o;
    }
}

// x part (cols 128..255) as hi/lo; zero pad rows entirely
__global__ void xsplit_kernel(const float* __restrict__ x) {
    size_t idx = (size_t)blockIdx.x * 256 + threadIdx.x;   // float4 index
    if (idx >= (size_t)NPAD * 32) return;
    int m = (int)(idx >> 5);
    int q = (int)(idx & 31);
    float4 v = make_float4(0.f, 0.f, 0.f, 0.f);
    if (m < NNODES) v = ((const float4*)x)[(size_t)m * 32 + q];
    float vv[4] = {v.x, v.y, v.z, v.w};
    __nv_bfloat16 hi[4], lo[4];
#pragma unroll
    for (int j = 0; j < 4; ++j) {
        hi[j] = __float2bfloat16(vv[j]);
        lo[j] = __float2bfloat16(vv[j] - __bfloat162float(hi[j]));
    }
    *(uint2*)(g_ahi + (size_t)m * 256 + 128 + q * 4) = *(const uint2*)hi;
    *(uint2*)(g_alo + (size_t)m * 256 + 128 + q * 4) = *(const uint2*)lo;
    if (m >= NNODES) {   // zero the mean half of pad rows
        uint2 z = make_uint2(0u, 0u);
        *(uint2*)(g_ahi + (size_t)m * 256 + q * 4) = z;
        *(uint2*)(g_alo + (size_t)m * 256 + q * 4) = z;
    }
}

__global__ void prep_weights(const float* __restrict__ W1l, const float* __restrict__ W1r,
                             const float* __restrict__ W2l, const float* __restrict__ W2r) {
    int j = blockIdx.x;    // out dim
    int k = threadIdx.x;   // in dim
    float w1 = (k < 128) ? W1l[j * 128 + k] : W1r[j * 128 + (k - 128)];
    float w2 = (j < 128) ? W2l[j * 256 + k] : W2r[(j - 128) * 256 + k];
    __nv_bfloat16 h1 = __float2bfloat16(w1);
    __nv_bfloat16 h2 = __float2bfloat16(w2);
    g_w1hi[j * 256 + k] = h1;
    g_w1lo[j * 256 + k] = __float2bfloat16(w1 - __bfloat162float(h1));
    g_w2hi[j * 256 + k] = h2;
    g_w2lo[j * 256 + k] = __float2bfloat16(w2 - __bfloat162float(h2));
}

// ---------------- mma.sync GEMM ----------------
#define TILE_B   10240      // 128 * 80
#define STAGE_B  40960
#define GEMM_SMEM 81920

__device__ __forceinline__ void cp_stage(uint32_t sb,
    const __nv_bfloat16* Ahi, const __nv_bfloat16* Alo,
    const __nv_bfloat16* Whi, const __nv_bfloat16* Wlo,
    int row0, int nbase, int kt, int st, int tid) {
#pragma unroll
    for (int i = 0; i < 8; ++i) {
        int c = i * 256 + tid;          // 0..2047
        int tile = c >> 9;              // 0:Ahi 1:Alo 2:Whi 3:Wlo
        int idx  = c & 511;
        int row  = idx >> 2;
        int kc   = idx & 3;
        uint32_t dst = sb + st * STAGE_B + tile * TILE_B
                     + (uint32_t)(row * 80 + kc * 16);
        const __nv_bfloat16* g;
        if (tile == 0)      g = Ahi + (size_t)(row0 + row) * 256;
        else if (tile == 1) g = Alo + (size_t)(row0 + row) * 256;
        else if (tile == 2) g = Whi + (size_t)(nbase + row) * 256;
        else                g = Wlo + (size_t)(nbase + row) * 256;
        g += kt * 32 + kc * 8;
        CP_ASYNC16(dst, g);
    }
}

__global__ void __launch_bounds__(256, 2) gemm_mma(int layer,
                                                   const float* __restrict__ b1v,
                                                   const float* __restrict__ b2v,
                                                   float* __restrict__ dout) {
    extern __shared__ char dsm[];
    int tid = threadIdx.x, lane = tid & 31, wid = tid >> 5;
    int row0 = blockIdx.x * 128;
    int by   = blockIdx.y;
    int nbase = by * 128;

    const __nv_bfloat16* Ahi = (layer == 1) ? g_ahi : g_bhi;
    const __nv_bfloat16* Alo = (layer == 1) ? g_alo : g_blo;
    const __nv_bfloat16* Whi = (layer == 1) ? g_w1hi : g_w2hi;
    const __nv_bfloat16* Wlo = (layer == 1) ? g_w1lo : g_w2lo;

    uint32_t sb = smem_u32(dsm);
    int mrow = (wid >> 1) * 32;
    int ncol = (wid & 1) * 64;

    float acc[2][8][4];
#pragma unroll
    for (int mt = 0; mt < 2; ++mt)
#pragma unroll
        for (int j = 0; j < 8; ++j)
#pragma unroll
            for (int q = 0; q < 4; ++q) acc[mt][j][q] = 0.f;

    cp_stage(sb, Ahi, Alo, Whi, Wlo, row0, nbase, 0, 0, tid);
    CP_COMMIT();

    for (int kt = 0; kt < 8; ++kt) {
        int st = kt & 1;
        CP_WAIT0();
        __syncthreads();
        if (kt < 7) {
            cp_stage(sb, Ahi, Alo, Whi, Wlo, row0, nbase, kt + 1, st ^ 1, tid);
            CP_COMMIT();
        }
        const char* sa = dsm + st * STAGE_B;
#pragma unroll
        for (int ks = 0; ks < 2; ++ks) {
            uint32_t a_base = (uint32_t)((mrow + (lane >> 2)) * 80
                                         + (lane & 3) * 4 + ks * 32);
            uint32_t ah[2][4], al[2][4];
#pragma unroll
            for (int mt = 0; mt < 2; ++mt) {
                uint32_t o = a_base + mt * 1280;
                ah[mt][0] = *(const uint32_t*)(sa + o);
                ah[mt][1] = *(const uint32_t*)(sa + o + 640);
                ah[mt][2] = *(const uint32_t*)(sa + o + 16);
                ah[mt][3] = *(const uint32_t*)(sa + o + 656);
                al[mt][0] = *(const uint32_t*)(sa + TILE_B + o);
                al[mt][1] = *(const uint32_t*)(sa + TILE_B + o + 640);
                al[mt][2] = *(const uint32_t*)(sa + TILE_B + o + 16);
                al[mt][3] = *(const uint32_t*)(sa + TILE_B + o + 656);
            }
            uint32_t b_base = (uint32_t)((ncol + (lane >> 2)) * 80
                                         + (lane & 3) * 4 + ks * 32);
#pragma unroll
            for (int j = 0; j < 8; ++j) {
                uint32_t o = b_base + j * 640;
                uint32_t bh0 = *(const uint32_t*)(sa + 2 * TILE_B + o);
                uint32_t bh1 = *(const uint32_t*)(sa + 2 * TILE_B + o + 16);
                uint32_t bl0 = *(const uint32_t*)(sa + 3 * TILE_B + o);
                uint32_t bl1 = *(const uint32_t*)(sa + 3 * TILE_B + o + 16);
#pragma unroll
                for (int mt = 0; mt < 2; ++mt) {
                    MMA_BF16(acc[mt][j], ah[mt], bh0, bh1);
                    MMA_BF16(acc[mt][j], al[mt], bh0, bh1);
                    MMA_BF16(acc[mt][j], ah[mt], bl0, bl1);
                }
            }
        }
        __syncthreads();
    }

    int r_base  = row0 + mrow + (lane >> 2);
    int cl_base = ncol + (lane & 3) * 2;
    if (layer == 1) {
#pragma unroll
        for (int mt = 0; mt < 2; ++mt)
#pragma unroll
            for (int j = 0; j < 8; ++j) {
                int gn = nbase + cl_base + j * 8;
                float bx0 = b1v[gn], bx1 = b1v[gn + 1];
#pragma unroll
                for (int hh = 0; hh < 2; ++hh) {
                    int r = r_base + mt * 16 + hh * 8;
                    float v0 = fmaxf(acc[mt][j][hh * 2]     + bx0, 0.f);
                    float v1 = fmaxf(acc[mt][j][hh * 2 + 1] + bx1, 0.f);
                    __nv_bfloat16 h0 = __float2bfloat16(v0);
                    __nv_bfloat16 h1 = __float2bfloat16(v1);
                    __nv_bfloat16 l0 = __float2bfloat16(v0 - __bfloat162float(h0));
                    __nv_bfloat16 l1 = __float2bfloat16(v1 - __bfloat162float(h1));
                    __nv_bfloat16 hp[2] = {h0, h1};
                    __nv_bfloat16 lp[2] = {l0, l1};
                    *(uint32_t*)(g_bhi + (size_t)r * 256 + gn) = *(const uint32_t*)hp;
                    *(uint32_t*)(g_blo + (size_t)r * 256 + gn) = *(const uint32_t*)lp;
                }
            }
    } else {
#pragma unroll
        for (int mt = 0; mt < 2; ++mt)
#pragma unroll
            for (int j = 0; j < 8; ++j) {
                int cl = cl_base + j * 8;
#pragma unroll
                for (int hh = 0; hh < 2; ++hh) {
                    int r = r_base + mt * 16 + hh * 8;
                    float v0 = acc[mt][j][hh * 2];
                    float v1 = acc[mt][j][hh * 2 + 1];
                    if (by == 0) {
                        float2 w = make_float2(v0, v1);
                        *(float2*)(g_p + (size_t)r * 128 + cl) = w;
                    } else if (r < NNODES) {
                        float2 w = make_float2(v0 + b2v[cl], v1 + b2v[cl + 1]);
                        *(float2*)(dout + (size_t)r * 128 + cl) = w;
                    }
                }
            }
    }
}

extern "C" void kernel_launch(void* const* d_in, const int* in_sizes, int n_in,
                              void* d_out, int out_size) {
    const float* x   = (const float*)d_in[0];
    const void*  ei  = d_in[1];
    const float* W1l = (const float*)d_in[2];
    const float* b1  = (const float*)d_in[3];
    const float* W1r = (const float*)d_in[4];
    const float* W2l = (const float*)d_in[5];
    const float* b2  = (const float*)d_in[6];
    const float* W2r = (const float*)d_in[7];
    float* out = (float*)d_out;

    cudaFuncSetAttribute(gemm_mma, cudaFuncAttributeMaxDynamicSharedMemorySize,
                         GEMM_SMEM);

    // CSR build (once) + weight prep
    detect_kernel<<<1, 256>>>((const int*)ei);
    zero_wix<<<(NNODES + 255) / 256, 256>>>();
    count_kernel<<<(NEDGES + 255) / 256, 256>>>(ei);
    blocksum_kernel<<<SCAN_BLOCKS, 1024>>>();
    scan_bsum<<<1, 128>>>();
    rowptr_kernel<<<SCAN_BLOCKS, 1024>>>();
    scatter_kernel<<<(NEDGES + 255) / 256, 256>>>(ei);
    prep_weights<<<256, 256>>>(W1l, W1r, W2l, W2r);

    // layer 1: gather-mean(x) -> g_ahi/alo[:,0:128); x -> cols [128,256)
    gather_kernel<<<12500, 256>>>(x, out, 0);
    xsplit_kernel<<<(unsigned)(((size_t)NPAD * 32 + 255) / 256), 256>>>(x);
    gemm_mma<<<dim3(NBM, 2), 256, GEMM_SMEM>>>(1, b1, b2, out);

    // layer 2: GEMM (p -> g_p, r + b2 -> out), then out += gather-mean(p)
    gemm_mma<<<dim3(NBM, 2), 256, GEMM_SMEM>>>(2, b1, b2, out);
    gather_kernel<<<12500, 256>>>(x, out, 1);
}

// round 9
// speedup vs baseline: 3.4652x; 1.0504x over previous
#include <cuda_runtime.h>
#include <cuda_bf16.h>
#include <cstdint>
#include <cstddef>

#define NNODES 100000
#define NPAD   100096           // 782 * 128
#define NEDGES 1600000
#define NBM    782              // NPAD / 128
#define SCAN_BLOCKS 98          // 98 * 1024 >= NNODES

// ---------------- scratch (device globals) ----------------
__device__ __align__(16) float g_p   [(size_t)NPAD * 128];
__device__ __align__(16) __nv_bfloat16 g_ahi[(size_t)NPAD * 256];  // layer1 input hi
__device__ __align__(16) __nv_bfloat16 g_alo[(size_t)NPAD * 256];  // layer1 input lo
__device__ __align__(16) __nv_bfloat16 g_bhi[(size_t)NPAD * 256];  // layer2 input hi
__device__ __align__(16) __nv_bfloat16 g_blo[(size_t)NPAD * 256];  // layer2 input lo
__device__ __align__(16) __nv_bfloat16 g_w1hi[256 * 256];
__device__ __align__(16) __nv_bfloat16 g_w1lo[256 * 256];
__device__ __align__(16) __nv_bfloat16 g_w2hi[256 * 256];
__device__ __align__(16) __nv_bfloat16 g_w2lo[256 * 256];
__device__ int g_rowptr[NNODES + 1];
__device__ int g_wix[NNODES];
__device__ int g_srcidx[NEDGES];
__device__ int g_bsum[SCAN_BLOCKS];
__device__ int g_boff[SCAN_BLOCKS];
__device__ int g_is64;

__device__ __forceinline__ uint32_t smem_u32(const void* p) {
    uint32_t a;
    asm("{ .reg .u64 t; cvta.to.shared.u64 t, %1; cvt.u32.u64 %0, t; }"
        : "=r"(a) : "l"(p));
    return a;
}

#define MMA_BF16(c, a, b0, b1) \
    asm volatile("mma.sync.aligned.m16n8k16.row.col.f32.bf16.bf16.f32 " \
        "{%0,%1,%2,%3}, {%4,%5,%6,%7}, {%8,%9}, {%0,%1,%2,%3};" \
        : "+f"((c)[0]), "+f"((c)[1]), "+f"((c)[2]), "+f"((c)[3]) \
        : "r"((a)[0]), "r"((a)[1]), "r"((a)[2]), "r"((a)[3]), "r"(b0), "r"(b1))

#define CP_ASYNC16(dst, src) \
    asm volatile("cp.async.cg.shared.global [%0], [%1], 16;" \
                 :: "r"(dst), "l"(src) : "memory")
#define CP_COMMIT() asm volatile("cp.async.commit_group;" ::: "memory")
#define CP_WAIT0()  asm volatile("cp.async.wait_group 0;" ::: "memory")

// ---------------- edge index decode ----------------
__device__ __forceinline__ void load_edge(const void* ei, int e, int& s, int& t) {
    if (g_is64) {
        const long long* e64 = (const long long*)ei;
        s = (int)e64[e];
        t = (int)e64[(size_t)NEDGES + e];
    } else {
        const int* e32 = (const int*)ei;
        s = e32[e];
        t = e32[(size_t)NEDGES + e];
    }
}

__global__ void detect_kernel(const int* __restrict__ ei32) {
    __shared__ int sOr;
    if (threadIdx.x == 0) sOr = 0;
    __syncthreads();
    int acc = 0;
    for (int i = threadIdx.x; i < 2048; i += blockDim.x) acc |= ei32[2 * i + 1];
    atomicOr(&sOr, acc);
    __syncthreads();
    if (threadIdx.x == 0) g_is64 = (sOr == 0) ? 1 : 0;
}

// ---------------- CSR build (by target) ----------------
__global__ void zero_wix() {
    int i = blockIdx.x * blockDim.x + threadIdx.x;
    if (i < NNODES) g_wix[i] = 0;
}

__global__ void count_kernel(const void* __restrict__ ei) {
    int e = blockIdx.x * blockDim.x + threadIdx.x;
    if (e >= NEDGES) return;
    int s, t;
    load_edge(ei, e, s, t);
    if ((unsigned)s >= NNODES || (unsigned)t >= NNODES) return;
    atomicAdd(&g_wix[t], 1);
}

__global__ void blocksum_kernel() {
    __shared__ int red[32];
    int idx = blockIdx.x * 1024 + threadIdx.x;
    int v = (idx < NNODES) ? g_wix[idx] : 0;
#pragma unroll
    for (int o = 16; o > 0; o >>= 1) v += __shfl_down_sync(0xFFFFFFFFu, v, o);
    if ((threadIdx.x & 31) == 0) red[threadIdx.x >> 5] = v;
    __syncthreads();
    if (threadIdx.x < 32) {
        int w = red[threadIdx.x];
#pragma unroll
        for (int o = 16; o > 0; o >>= 1) w += __shfl_down_sync(0xFFFFFFFFu, w, o);
        if (threadIdx.x == 0) g_bsum[blockIdx.x] = w;
    }
}

__global__ void scan_bsum() {
    __shared__ int s[SCAN_BLOCKS];
    int tid = threadIdx.x;
    if (tid < SCAN_BLOCKS) s[tid] = g_bsum[tid];
    __syncthreads();
    if (tid == 0) {
        int run = 0;
        for (int i = 0; i < SCAN_BLOCKS; ++i) {
            g_boff[i] = run;
            run += s[i];
        }
        g_rowptr[NNODES] = run;
    }
}

__global__ void rowptr_kernel() {
    __shared__ int sc[1024];
    int tid = threadIdx.x;
    int idx = blockIdx.x * 1024 + tid;
    int v = (idx < NNODES) ? g_wix[idx] : 0;
    sc[tid] = v;
    __syncthreads();
#pragma unroll
    for (int off = 1; off < 1024; off <<= 1) {
        int u = (tid >= off) ? sc[tid - off] : 0;
        __syncthreads();
        sc[tid] += u;
        __syncthreads();
    }
    if (idx < NNODES) {
        int excl = sc[tid] - v + g_boff[blockIdx.x];
        g_rowptr[idx] = excl;
        g_wix[idx] = excl;
    }
}

__global__ void scatter_kernel(const void* __restrict__ ei) {
    int e = blockIdx.x * blockDim.x + threadIdx.x;
    if (e >= NEDGES) return;
    int s, t;
    load_edge(ei, e, s, t);
    if ((unsigned)s >= NNODES || (unsigned)t >= NNODES) return;
    int pos = atomicAdd(&g_wix[t], 1);
    g_srcidx[pos] = s;
}

// ---------------- gather aggregation: one warp per node, MLP-8 ----------------
// phase 0: mean of x rows -> hi/lo cols [0,128); x[node] -> hi/lo cols [128,256)
// phase 1: mean of g_p rows -> out[node] += mean
__global__ void gather_kernel(const float* __restrict__ x,
                              float* __restrict__ out, int phase) {
    int node = (int)(((size_t)blockIdx.x * blockDim.x + threadIdx.x) >> 5);
    int lane = threadIdx.x & 31;
    if (node >= NNODES) return;
    int beg = g_rowptr[node];
    int end = g_rowptr[node + 1];
    const float* src = (phase == 0) ? x : g_p;

    float4 acc = make_float4(0.f, 0.f, 0.f, 0.f);
    int i = beg;
    for (; i + 7 < end; i += 8) {
        int sx[8];
#pragma unroll
        for (int u = 0; u < 8; ++u) sx[u] = g_srcidx[i + u];
        float4 v[8];
#pragma unroll
        for (int u = 0; u < 8; ++u)
            v[u] = ((const float4*)(src + ((size_t)sx[u] << 7)))[lane];
#pragma unroll
        for (int u = 0; u < 8; ++u) {
            acc.x += v[u].x; acc.y += v[u].y;
            acc.z += v[u].z; acc.w += v[u].w;
        }
    }
    if (i + 3 < end) {
        int sx[4];
#pragma unroll
        for (int u = 0; u < 4; ++u) sx[u] = g_srcidx[i + u];
        float4 v[4];
#pragma unroll
        for (int u = 0; u < 4; ++u)
            v[u] = ((const float4*)(src + ((size_t)sx[u] << 7)))[lane];
#pragma unroll
        for (int u = 0; u < 4; ++u) {
            acc.x += v[u].x; acc.y += v[u].y;
            acc.z += v[u].z; acc.w += v[u].w;
        }
        i += 4;
    }
    for (; i < end; ++i) {
        int s0 = g_srcidx[i];
        float4 v0 = ((const float4*)(src + ((size_t)s0 << 7)))[lane];
        acc.x += v0.x; acc.y += v0.y; acc.z += v0.z; acc.w += v0.w;
    }
    float rdeg = 1.0f / fmaxf((float)(end - beg), 1.0f);
    float vv[4] = {acc.x * rdeg, acc.y * rdeg, acc.z * rdeg, acc.w * rdeg};

    if (phase == 0) {
        __nv_bfloat16 hi[4], lo[4];
#pragma unroll
        for (int j = 0; j < 4; ++j) {
            hi[j] = __float2bfloat16(vv[j]);
            lo[j] = __float2bfloat16(vv[j] - __bfloat162float(hi[j]));
        }
        *(uint2*)(g_ahi + (size_t)node * 256 + lane * 4) = *(const uint2*)hi;
        *(uint2*)(g_alo + (size_t)node * 256 + lane * 4) = *(const uint2*)lo;
        // fused xsplit: x[node] -> cols [128,256)
        float4 xr = ((const float4*)(x + ((size_t)node << 7)))[lane];
        float xv[4] = {xr.x, xr.y, xr.z, xr.w};
#pragma unroll
        for (int j = 0; j < 4; ++j) {
            hi[j] = __float2bfloat16(xv[j]);
            lo[j] = __float2bfloat16(xv[j] - __bfloat162float(hi[j]));
        }
        *(uint2*)(g_ahi + (size_t)node * 256 + 128 + lane * 4) = *(const uint2*)hi;
        *(uint2*)(g_alo + (size_t)node * 256 + 128 + lane * 4) = *(const uint2*)lo;
    } else {
        float4* op = (float4*)out + (size_t)node * 32 + lane;
        float4 o = *op;
        o.x += vv[0]; o.y += vv[1]; o.z += vv[2]; o.w += vv[3];
        *op = o;
    }
}

// zero the 96 pad rows of g_ahi/g_alo (all 256 cols)
__global__ void pad_kernel() {
    int r = NNODES + blockIdx.x;            // 96 blocks
    int q = threadIdx.x;                     // 64 threads: uint2 = 4 bf16
    uint2 z = make_uint2(0u, 0u);
    *(uint2*)(g_ahi + (size_t)r * 256 + q * 4) = z;
    *(uint2*)(g_alo + (size_t)r * 256 + q * 4) = z;
}

__global__ void prep_weights(const float* __restrict__ W1l, const float* __restrict__ W1r,
                             const float* __restrict__ W2l, const float* __restrict__ W2r) {
    int j = blockIdx.x;    // out dim
    int k = threadIdx.x;   // in dim
    float w1 = (k < 128) ? W1l[j * 128 + k] : W1r[j * 128 + (k - 128)];
    float w2 = (j < 128) ? W2l[j * 256 + k] : W2r[(j - 128) * 256 + k];
    __nv_bfloat16 h1 = __float2bfloat16(w1);
    __nv_bfloat16 h2 = __float2bfloat16(w2);
    g_w1hi[j * 256 + k] = h1;
    g_w1lo[j * 256 + k] = __float2bfloat16(w1 - __bfloat162float(h1));
    g_w2hi[j * 256 + k] = h2;
    g_w2lo[j * 256 + k] = __float2bfloat16(w2 - __bfloat162float(h2));
}

// ---------------- mma.sync GEMM ----------------
#define TILE_B   10240      // 128 * 80
#define STAGE_B  40960
#define GEMM_SMEM 81920

__device__ __forceinline__ void cp_stage(uint32_t sb,
    const __nv_bfloat16* Ahi, const __nv_bfloat16* Alo,
    const __nv_bfloat16* Whi, const __nv_bfloat16* Wlo,
    int row0, int nbase, int kt, int st, int tid) {
#pragma unroll
    for (int i = 0; i < 8; ++i) {
        int c = i * 256 + tid;          // 0..2047
        int tile = c >> 9;              // 0:Ahi 1:Alo 2:Whi 3:Wlo
        int idx  = c & 511;
        int row  = idx >> 2;
        int kc   = idx & 3;
        uint32_t dst = sb + st * STAGE_B + tile * TILE_B
                     + (uint32_t)(row * 80 + kc * 16);
        const __nv_bfloat16* g;
        if (tile == 0)      g = Ahi + (size_t)(row0 + row) * 256;
        else if (tile == 1) g = Alo + (size_t)(row0 + row) * 256;
        else if (tile == 2) g = Whi + (size_t)(nbase + row) * 256;
        else                g = Wlo + (size_t)(nbase + row) * 256;
        g += kt * 32 + kc * 8;
        CP_ASYNC16(dst, g);
    }
}

__global__ void __launch_bounds__(256, 2) gemm_mma(int layer,
                                                   const float* __restrict__ b1v,
                                                   const float* __restrict__ b2v,
                                                   float* __restrict__ dout) {
    extern __shared__ char dsm[];
    int tid = threadIdx.x, lane = tid & 31, wid = tid >> 5;
    int row0 = blockIdx.x * 128;
    int by   = blockIdx.y;
    int nbase = by * 128;

    const __nv_bfloat16* Ahi = (layer == 1) ? g_ahi : g_bhi;
    const __nv_bfloat16* Alo = (layer == 1) ? g_alo : g_blo;
    const __nv_bfloat16* Whi = (layer == 1) ? g_w1hi : g_w2hi;
    const __nv_bfloat16* Wlo = (layer == 1) ? g_w1lo : g_w2lo;

    uint32_t sb = smem_u32(dsm);
    int mrow = (wid >> 1) * 32;
    int ncol = (wid & 1) * 64;

    float acc[2][8][4];
#pragma unroll
    for (int mt = 0; mt < 2; ++mt)
#pragma unroll
        for (int j = 0; j < 8; ++j)
#pragma unroll
            for (int q = 0; q < 4; ++q) acc[mt][j][q] = 0.f;

    cp_stage(sb, Ahi, Alo, Whi, Wlo, row0, nbase, 0, 0, tid);
    CP_COMMIT();

    for (int kt = 0; kt < 8; ++kt) {
        int st = kt & 1;
        CP_WAIT0();
        __syncthreads();
        if (kt < 7) {
            cp_stage(sb, Ahi, Alo, Whi, Wlo, row0, nbase, kt + 1, st ^ 1, tid);
            CP_COMMIT();
        }
        const char* sa = dsm + st * STAGE_B;
#pragma unroll
        for (int ks = 0; ks < 2; ++ks) {
            uint32_t a_base = (uint32_t)((mrow + (lane >> 2)) * 80
                                         + (lane & 3) * 4 + ks * 32);
            uint32_t ah[2][4], al[2][4];
#pragma unroll
            for (int mt = 0; mt < 2; ++mt) {
                uint32_t o = a_base + mt * 1280;
                ah[mt][0] = *(const uint32_t*)(sa + o);
                ah[mt][1] = *(const uint32_t*)(sa + o + 640);
                ah[mt][2] = *(const uint32_t*)(sa + o + 16);
                ah[mt][3] = *(const uint32_t*)(sa + o + 656);
                al[mt][0] = *(const uint32_t*)(sa + TILE_B + o);
                al[mt][1] = *(const uint32_t*)(sa + TILE_B + o + 640);
                al[mt][2] = *(const uint32_t*)(sa + TILE_B + o + 16);
                al[mt][3] = *(const uint32_t*)(sa + TILE_B + o + 656);
            }
            uint32_t b_base = (uint32_t)((ncol + (lane >> 2)) * 80
                                         + (lane & 3) * 4 + ks * 32);
#pragma unroll
            for (int j = 0; j < 8; ++j) {
                uint32_t o = b_base + j * 640;
                uint32_t bh0 = *(const uint32_t*)(sa + 2 * TILE_B + o);
                uint32_t bh1 = *(const uint32_t*)(sa + 2 * TILE_B + o + 16);
                uint32_t bl0 = *(const uint32_t*)(sa + 3 * TILE_B + o);
                uint32_t bl1 = *(const uint32_t*)(sa + 3 * TILE_B + o + 16);
#pragma unroll
                for (int mt = 0; mt < 2; ++mt) {
                    MMA_BF16(acc[mt][j], ah[mt], bh0, bh1);
                    MMA_BF16(acc[mt][j], al[mt], bh0, bh1);
                    MMA_BF16(acc[mt][j], ah[mt], bl0, bl1);
                }
            }
        }
        __syncthreads();
    }

    int r_base  = row0 + mrow + (lane >> 2);
    int cl_base = ncol + (lane & 3) * 2;
    if (layer == 1) {
#pragma unroll
        for (int mt = 0; mt < 2; ++mt)
#pragma unroll
            for (int j = 0; j < 8; ++j) {
                int gn = nbase + cl_base + j * 8;
                float bx0 = b1v[gn], bx1 = b1v[gn + 1];
#pragma unroll
                for (int hh = 0; hh < 2; ++hh) {
                    int r = r_base + mt * 16 + hh * 8;
                    float v0 = fmaxf(acc[mt][j][hh * 2]     + bx0, 0.f);
                    float v1 = fmaxf(acc[mt][j][hh * 2 + 1] + bx1, 0.f);
                    __nv_bfloat16 h0 = __float2bfloat16(v0);
                    __nv_bfloat16 h1 = __float2bfloat16(v1);
                    __nv_bfloat16 l0 = __float2bfloat16(v0 - __bfloat162float(h0));
                    __nv_bfloat16 l1 = __float2bfloat16(v1 - __bfloat162float(h1));
                    __nv_bfloat16 hp[2] = {h0, h1};
                    __nv_bfloat16 lp[2] = {l0, l1};
                    *(uint32_t*)(g_bhi + (size_t)r * 256 + gn) = *(const uint32_t*)hp;
                    *(uint32_t*)(g_blo + (size_t)r * 256 + gn) = *(const uint32_t*)lp;
                }
            }
    } else {
#pragma unroll
        for (int mt = 0; mt < 2; ++mt)
#pragma unroll
            for (int j = 0; j < 8; ++j) {
                int cl = cl_base + j * 8;
#pragma unroll
                for (int hh = 0; hh < 2; ++hh) {
                    int r = r_base + mt * 16 + hh * 8;
                    float v0 = acc[mt][j][hh * 2];
                    float v1 = acc[mt][j][hh * 2 + 1];
                    if (by == 0) {
                        float2 w = make_float2(v0, v1);
                        *(float2*)(g_p + (size_t)r * 128 + cl) = w;
                    } else if (r < NNODES) {
                        float2 w = make_float2(v0 + b2v[cl], v1 + b2v[cl + 1]);
                        *(float2*)(dout + (size_t)r * 128 + cl) = w;
                    }
                }
            }
    }
}

extern "C" void kernel_launch(void* const* d_in, const int* in_sizes, int n_in,
                              void* d_out, int out_size) {
    const float* x   = (const float*)d_in[0];
    const void*  ei  = d_in[1];
    const float* W1l = (const float*)d_in[2];
    const float* b1  = (const float*)d_in[3];
    const float* W1r = (const float*)d_in[4];
    const float* W2l = (const float*)d_in[5];
    const float* b2  = (const float*)d_in[6];
    const float* W2r = (const float*)d_in[7];
    float* out = (float*)d_out;

    cudaFuncSetAttribute(gemm_mma, cudaFuncAttributeMaxDynamicSharedMemorySize,
                         GEMM_SMEM);

    // CSR build (once) + weight prep
    detect_kernel<<<1, 256>>>((const int*)ei);
    zero_wix<<<(NNODES + 255) / 256, 256>>>();
    count_kernel<<<(NEDGES + 255) / 256, 256>>>(ei);
    blocksum_kernel<<<SCAN_BLOCKS, 1024>>>();
    scan_bsum<<<1, 128>>>();
    rowptr_kernel<<<SCAN_BLOCKS, 1024>>>();
    scatter_kernel<<<(NEDGES + 255) / 256, 256>>>(ei);
    prep_weights<<<256, 256>>>(W1l, W1r, W2l, W2r);
    pad_kernel<<<NPAD - NNODES, 64>>>();

    // layer 1: gather-mean(x)+xsplit -> g_ahi/g_alo, then GEMM
    gather_kernel<<<12500, 256>>>(x, out, 0);
    gemm_mma<<<dim3(NBM, 2), 256, GEMM_SMEM>>>(1, b1, b2, out);

    // layer 2: GEMM (p -> g_p, r + b2 -> out), then out += gather-mean(p)
    gemm_mma<<<dim3(NBM, 2), 256, GEMM_SMEM>>>(2, b1, b2, out);
    gather_kernel<<<12500, 256>>>(x, out, 1);
}

// round 10
// speedup vs baseline: 4.2606x; 1.2295x over previous
#include <cuda_runtime.h>
#include <cuda_fp16.h>
#include <cstdint>
#include <cstddef>

#define NNODES 100000
#define NPAD   100096           // 782 * 128
#define NEDGES 1600000
#define NBM    782              // NPAD / 128
#define SCAN_BLOCKS 98          // 98 * 1024 >= NNODES

// ---------------- scratch (device globals) ----------------
__device__ __align__(16) float g_p   [(size_t)NPAD * 128];
__device__ __align__(16) __half g_a  [(size_t)NPAD * 256];   // layer1 input fp16
__device__ __align__(16) __half g_b  [(size_t)NPAD * 256];   // layer2 input fp16
__device__ __align__(16) __half g_w1hi[256 * 256];
__device__ __align__(16) __half g_w1lo[256 * 256];
__device__ __align__(16) __half g_w2hi[256 * 256];
__device__ __align__(16) __half g_w2lo[256 * 256];
__device__ int g_rowptr[NNODES + 1];
__device__ int g_wix[NNODES];
__device__ int g_srcidx[NEDGES];
__device__ int g_bsum[SCAN_BLOCKS];
__device__ int g_boff[SCAN_BLOCKS];
__device__ int g_is64;

__device__ __forceinline__ uint32_t smem_u32(const void* p) {
    uint32_t a;
    asm("{ .reg .u64 t; cvta.to.shared.u64 t, %1; cvt.u32.u64 %0, t; }"
        : "=r"(a) : "l"(p));
    return a;
}

#define MMA_F16(c, a, b0, b1) \
    asm volatile("mma.sync.aligned.m16n8k16.row.col.f32.f16.f16.f32 " \
        "{%0,%1,%2,%3}, {%4,%5,%6,%7}, {%8,%9}, {%0,%1,%2,%3};" \
        : "+f"((c)[0]), "+f"((c)[1]), "+f"((c)[2]), "+f"((c)[3]) \
        : "r"((a)[0]), "r"((a)[1]), "r"((a)[2]), "r"((a)[3]), "r"(b0), "r"(b1))

#define CP_ASYNC16(dst, src) \
    asm volatile("cp.async.cg.shared.global [%0], [%1], 16;" \
                 :: "r"(dst), "l"(src) : "memory")
#define CP_COMMIT() asm volatile("cp.async.commit_group;" ::: "memory")
#define CP_WAIT0()  asm volatile("cp.async.wait_group 0;" ::: "memory")

// ---------------- edge index decode ----------------
__device__ __forceinline__ void load_edge(const void* ei, int e, int& s, int& t) {
    if (g_is64) {
        const long long* e64 = (const long long*)ei;
        s = (int)e64[e];
        t = (int)e64[(size_t)NEDGES + e];
    } else {
        const int* e32 = (const int*)ei;
        s = e32[e];
        t = e32[(size_t)NEDGES + e];
    }
}

__global__ void detect_kernel(const int* __restrict__ ei32) {
    __shared__ int sOr;
    if (threadIdx.x == 0) sOr = 0;
    __syncthreads();
    int acc = 0;
    for (int i = threadIdx.x; i < 2048; i += blockDim.x) acc |= ei32[2 * i + 1];
    atomicOr(&sOr, acc);
    __syncthreads();
    if (threadIdx.x == 0) g_is64 = (sOr == 0) ? 1 : 0;
}

// ---------------- CSR build (by target) ----------------
__global__ void zero_wix() {
    int i = blockIdx.x * blockDim.x + threadIdx.x;
    if (i < NNODES) g_wix[i] = 0;
}

__global__ void count_kernel(const void* __restrict__ ei) {
    int e = blockIdx.x * blockDim.x + threadIdx.x;
    if (e >= NEDGES) return;
    int s, t;
    load_edge(ei, e, s, t);
    if ((unsigned)s >= NNODES || (unsigned)t >= NNODES) return;
    atomicAdd(&g_wix[t], 1);
}

__global__ void blocksum_kernel() {
    __shared__ int red[32];
    int idx = blockIdx.x * 1024 + threadIdx.x;
    int v = (idx < NNODES) ? g_wix[idx] : 0;
#pragma unroll
    for (int o = 16; o > 0; o >>= 1) v += __shfl_down_sync(0xFFFFFFFFu, v, o);
    if ((threadIdx.x & 31) == 0) red[threadIdx.x >> 5] = v;
    __syncthreads();
    if (threadIdx.x < 32) {
        int w = red[threadIdx.x];
#pragma unroll
        for (int o = 16; o > 0; o >>= 1) w += __shfl_down_sync(0xFFFFFFFFu, w, o);
        if (threadIdx.x == 0) g_bsum[blockIdx.x] = w;
    }
}

__global__ void scan_bsum() {
    __shared__ int s[SCAN_BLOCKS];
    int tid = threadIdx.x;
    if (tid < SCAN_BLOCKS) s[tid] = g_bsum[tid];
    __syncthreads();
    if (tid == 0) {
        int run = 0;
        for (int i = 0; i < SCAN_BLOCKS; ++i) {
            g_boff[i] = run;
            run += s[i];
        }
        g_rowptr[NNODES] = run;
    }
}

__global__ void rowptr_kernel() {
    __shared__ int sc[1024];
    int tid = threadIdx.x;
    int idx = blockIdx.x * 1024 + tid;
    int v = (idx < NNODES) ? g_wix[idx] : 0;
    sc[tid] = v;
    __syncthreads();
#pragma unroll
    for (int off = 1; off < 1024; off <<= 1) {
        int u = (tid >= off) ? sc[tid - off] : 0;
        __syncthreads();
        sc[tid] += u;
        __syncthreads();
    }
    if (idx < NNODES) {
        int excl = sc[tid] - v + g_boff[blockIdx.x];
        g_rowptr[idx] = excl;
        g_wix[idx] = excl;
    }
}

__global__ void scatter_kernel(const void* __restrict__ ei) {
    int e = blockIdx.x * blockDim.x + threadIdx.x;
    if (e >= NEDGES) return;
    int s, t;
    load_edge(ei, e, s, t);
    if ((unsigned)s >= NNODES || (unsigned)t >= NNODES) return;
    int pos = atomicAdd(&g_wix[t], 1);
    g_srcidx[pos] = s;
}

// ---------------- gather aggregation: one warp per node, MLP-8 ----------------
// phase 0: mean of x rows -> fp16 cols [0,128); x[node] -> fp16 cols [128,256)
// phase 1: mean of g_p rows -> out[node] += mean
__global__ void gather_kernel(const float* __restrict__ x,
                              float* __restrict__ out, int phase) {
    int node = (int)(((size_t)blockIdx.x * blockDim.x + threadIdx.x) >> 5);
    int lane = threadIdx.x & 31;
    if (node >= NNODES) return;
    int beg = g_rowptr[node];
    int end = g_rowptr[node + 1];
    const float* src = (phase == 0) ? x : g_p;

    float4 acc = make_float4(0.f, 0.f, 0.f, 0.f);
    int i = beg;
    for (; i + 7 < end; i += 8) {
        int sx[8];
#pragma unroll
        for (int u = 0; u < 8; ++u) sx[u] = g_srcidx[i + u];
        float4 v[8];
#pragma unroll
        for (int u = 0; u < 8; ++u)
            v[u] = ((const float4*)(src + ((size_t)sx[u] << 7)))[lane];
#pragma unroll
        for (int u = 0; u < 8; ++u) {
            acc.x += v[u].x; acc.y += v[u].y;
            acc.z += v[u].z; acc.w += v[u].w;
        }
    }
    if (i + 3 < end) {
        int sx[4];
#pragma unroll
        for (int u = 0; u < 4; ++u) sx[u] = g_srcidx[i + u];
        float4 v[4];
#pragma unroll
        for (int u = 0; u < 4; ++u)
            v[u] = ((const float4*)(src + ((size_t)sx[u] << 7)))[lane];
#pragma unroll
        for (int u = 0; u < 4; ++u) {
            acc.x += v[u].x; acc.y += v[u].y;
            acc.z += v[u].z; acc.w += v[u].w;
        }
        i += 4;
    }
    for (; i < end; ++i) {
        int s0 = g_srcidx[i];
        float4 v0 = ((const float4*)(src + ((size_t)s0 << 7)))[lane];
        acc.x += v0.x; acc.y += v0.y; acc.z += v0.z; acc.w += v0.w;
    }
    float rdeg = 1.0f / fmaxf((float)(end - beg), 1.0f);
    float vv[4] = {acc.x * rdeg, acc.y * rdeg, acc.z * rdeg, acc.w * rdeg};

    if (phase == 0) {
        __half hm[4];
#pragma unroll
        for (int j = 0; j < 4; ++j) hm[j] = __float2half(vv[j]);
        *(uint2*)(g_a + (size_t)node * 256 + lane * 4) = *(const uint2*)hm;
        // fused xsplit: x[node] -> cols [128,256)
        float4 xr = ((const float4*)(x + ((size_t)node << 7)))[lane];
        float xv[4] = {xr.x, xr.y, xr.z, xr.w};
#pragma unroll
        for (int j = 0; j < 4; ++j) hm[j] = __float2half(xv[j]);
        *(uint2*)(g_a + (size_t)node * 256 + 128 + lane * 4) = *(const uint2*)hm;
    } else {
        float4* op = (float4*)out + (size_t)node * 32 + lane;
        float4 o = *op;
        o.x += vv[0]; o.y += vv[1]; o.z += vv[2]; o.w += vv[3];
        *op = o;
    }
}

// zero the 96 pad rows of g_a (all 256 cols)
__global__ void pad_kernel() {
    int r = NNODES + blockIdx.x;            // 96 blocks
    int q = threadIdx.x;                     // 64 threads x 4 halves
    uint2 z = make_uint2(0u, 0u);
    *(uint2*)(g_a + (size_t)r * 256 + q * 4) = z;
}

__global__ void prep_weights(const float* __restrict__ W1l, const float* __restrict__ W1r,
                             const float* __restrict__ W2l, const float* __restrict__ W2r) {
    int j = blockIdx.x;    // out dim
    int k = threadIdx.x;   // in dim
    float w1 = (k < 128) ? W1l[j * 128 + k] : W1r[j * 128 + (k - 128)];
    float w2 = (j < 128) ? W2l[j * 256 + k] : W2r[(j - 128) * 256 + k];
    __half h1 = __float2half(w1);
    __half h2 = __float2half(w2);
    g_w1hi[j * 256 + k] = h1;
    g_w1lo[j * 256 + k] = __float2half(w1 - __half2float(h1));
    g_w2hi[j * 256 + k] = h2;
    g_w2lo[j * 256 + k] = __float2half(w2 - __half2float(h2));
}

// ---------------- mma.sync GEMM: 2-term fp16 (A single, W hi/lo) ----------------
// SMEM stage (30720B): A, Whi, Wlo tiles of 128 rows x 32 fp16, rows padded
// to 80B (conflict-free fragment loads). Two stages, cp.async double buffering.
#define TILE_B   10240      // 128 * 80
#define STAGE_B  30720
#define GEMM_SMEM 61440

__device__ __forceinline__ void cp_stage(uint32_t sb,
    const __half* A, const __half* Whi, const __half* Wlo,
    int row0, int nbase, int kt, int st, int tid) {
#pragma unroll
    for (int i = 0; i < 6; ++i) {
        int c = i * 256 + tid;          // 0..1535
        int tile = c >> 9;              // 0:A 1:Whi 2:Wlo
        int idx  = c & 511;
        int row  = idx >> 2;
        int kc   = idx & 3;             // 16B chunk within 64B row
        uint32_t dst = sb + st * STAGE_B + tile * TILE_B
                     + (uint32_t)(row * 80 + kc * 16);
        const __half* g;
        if (tile == 0)      g = A   + (size_t)(row0 + row) * 256;
        else if (tile == 1) g = Whi + (size_t)(nbase + row) * 256;
        else                g = Wlo + (size_t)(nbase + row) * 256;
        g += kt * 32 + kc * 8;
        CP_ASYNC16(dst, g);
    }
}

__global__ void __launch_bounds__(256, 2) gemm_mma(int layer,
                                                   const float* __restrict__ b1v,
                                                   const float* __restrict__ b2v,
                                                   float* __restrict__ dout) {
    extern __shared__ char dsm[];
    int tid = threadIdx.x, lane = tid & 31, wid = tid >> 5;
    int row0 = blockIdx.x * 128;
    int by   = blockIdx.y;
    int nbase = by * 128;

    const __half* A   = (layer == 1) ? g_a : g_b;
    const __half* Whi = (layer == 1) ? g_w1hi : g_w2hi;
    const __half* Wlo = (layer == 1) ? g_w1lo : g_w2lo;

    uint32_t sb = smem_u32(dsm);
    int mrow = (wid >> 1) * 32;
    int ncol = (wid & 1) * 64;

    float acc[2][8][4];
#pragma unroll
    for (int mt = 0; mt < 2; ++mt)
#pragma unroll
        for (int j = 0; j < 8; ++j)
#pragma unroll
            for (int q = 0; q < 4; ++q) acc[mt][j][q] = 0.f;

    cp_stage(sb, A, Whi, Wlo, row0, nbase, 0, 0, tid);
    CP_COMMIT();

    for (int kt = 0; kt < 8; ++kt) {
        int st = kt & 1;
        CP_WAIT0();
        __syncthreads();
        if (kt < 7) {
            cp_stage(sb, A, Whi, Wlo, row0, nbase, kt + 1, st ^ 1, tid);
            CP_COMMIT();
        }
        const char* sa = dsm + st * STAGE_B;
#pragma unroll
        for (int ks = 0; ks < 2; ++ks) {
            uint32_t a_base = (uint32_t)((mrow + (lane >> 2)) * 80
                                         + (lane & 3) * 4 + ks * 32);
            uint32_t ah[2][4];
#pragma unroll
            for (int mt = 0; mt < 2; ++mt) {
                uint32_t o = a_base + mt * 1280;
                ah[mt][0] = *(const uint32_t*)(sa + o);
                ah[mt][1] = *(const uint32_t*)(sa + o + 640);
                ah[mt][2] = *(const uint32_t*)(sa + o + 16);
                ah[mt][3] = *(const uint32_t*)(sa + o + 656);
            }
            uint32_t b_base = (uint32_t)((ncol + (lane >> 2)) * 80
                                         + (lane & 3) * 4 + ks * 32);
#pragma unroll
            for (int j = 0; j < 8; ++j) {
                uint32_t o = b_base + j * 640;
                uint32_t bh0 = *(const uint32_t*)(sa + TILE_B + o);
                uint32_t bh1 = *(const uint32_t*)(sa + TILE_B + o + 16);
                uint32_t bl0 = *(const uint32_t*)(sa + 2 * TILE_B + o);
                uint32_t bl1 = *(const uint32_t*)(sa + 2 * TILE_B + o + 16);
#pragma unroll
                for (int mt = 0; mt < 2; ++mt) {
                    MMA_F16(acc[mt][j], ah[mt], bh0, bh1);
                    MMA_F16(acc[mt][j], ah[mt], bl0, bl1);
                }
            }
        }
        __syncthreads();
    }

    int r_base  = row0 + mrow + (lane >> 2);
    int cl_base = ncol + (lane & 3) * 2;
    if (layer == 1) {
        // h = relu(acc + b1) -> single fp16 into g_b (layer2 input)
#pragma unroll
        for (int mt = 0; mt < 2; ++mt)
#pragma unroll
            for (int j = 0; j < 8; ++j) {
                int gn = nbase + cl_base + j * 8;
                float bx0 = b1v[gn], bx1 = b1v[gn + 1];
#pragma unroll
                for (int hh = 0; hh < 2; ++hh) {
                    int r = r_base + mt * 16 + hh * 8;
                    float v0 = fmaxf(acc[mt][j][hh * 2]     + bx0, 0.f);
                    float v1 = fmaxf(acc[mt][j][hh * 2 + 1] + bx1, 0.f);
                    __half hp[2] = {__float2half(v0), __float2half(v1)};
                    *(uint32_t*)(g_b + (size_t)r * 256 + gn) = *(const uint32_t*)hp;
                }
            }
    } else {
#pragma unroll
        for (int mt = 0; mt < 2; ++mt)
#pragma unroll
            for (int j = 0; j < 8; ++j) {
                int cl = cl_base + j * 8;
#pragma unroll
                for (int hh = 0; hh < 2; ++hh) {
                    int r = r_base + mt * 16 + hh * 8;
                    float v0 = acc[mt][j][hh * 2];
                    float v1 = acc[mt][j][hh * 2 + 1];
                    if (by == 0) {
                        float2 w = make_float2(v0, v1);
                        *(float2*)(g_p + (size_t)r * 128 + cl) = w;
                    } else if (r < NNODES) {
                        float2 w = make_float2(v0 + b2v[cl], v1 + b2v[cl + 1]);
                        *(float2*)(dout + (size_t)r * 128 + cl) = w;
                    }
                }
            }
    }
}

extern "C" void kernel_launch(void* const* d_in, const int* in_sizes, int n_in,
                              void* d_out, int out_size) {
    const float* x   = (const float*)d_in[0];
    const void*  ei  = d_in[1];
    const float* W1l = (const float*)d_in[2];
    const float* b1  = (const float*)d_in[3];
    const float* W1r = (const float*)d_in[4];
    const float* W2l = (const float*)d_in[5];
    const float* b2  = (const float*)d_in[6];
    const float* W2r = (const float*)d_in[7];
    float* out = (float*)d_out;

    cudaFuncSetAttribute(gemm_mma, cudaFuncAttributeMaxDynamicSharedMemorySize,
                         GEMM_SMEM);

    // CSR build (once) + weight prep
    detect_kernel<<<1, 256>>>((const int*)ei);
    zero_wix<<<(NNODES + 255) / 256, 256>>>();
    count_kernel<<<(NEDGES + 255) / 256, 256>>>(ei);
    blocksum_kernel<<<SCAN_BLOCKS, 1024>>>();
    scan_bsum<<<1, 128>>>();
    rowptr_kernel<<<SCAN_BLOCKS, 1024>>>();
    scatter_kernel<<<(NEDGES + 255) / 256, 256>>>(ei);
    prep_weights<<<256, 256>>>(W1l, W1r, W2l, W2r);
    pad_kernel<<<NPAD - NNODES, 64>>>();

    // layer 1: gather-mean(x)+xsplit -> g_a, then GEMM -> g_b
    gather_kernel<<<12500, 256>>>(x, out, 0);
    gemm_mma<<<dim3(NBM, 2), 256, GEMM_SMEM>>>(1, b1, b2, out);

    // layer 2: GEMM (p -> g_p, r + b2 -> out), then out += gather-mean(p)
    gemm_mma<<<dim3(NBM, 2), 256, GEMM_SMEM>>>(2, b1, b2, out);
    gather_kernel<<<12500, 256>>>(x, out, 1);
}

// round 11
// speedup vs baseline: 4.4137x; 1.0359x over previous
#include <cuda_runtime.h>
#include <cuda_fp16.h>
#include <cstdint>
#include <cstddef>

#define NNODES 100000
#define NPAD   100096           // 782 * 128
#define NEDGES 1600000
#define NBM    782              // NPAD / 128
#define SCAN_BLOCKS 98          // 98 * 1024 >= NNODES

// ---------------- scratch (device globals) ----------------
__device__ __align__(16) __half g_p  [(size_t)NPAD * 128];   // h @ W2l^T in fp16
__device__ __align__(16) __half g_xh [(size_t)NNODES * 128]; // x in fp16
__device__ __align__(16) __half g_a  [(size_t)NPAD * 256];   // layer1 input fp16
__device__ __align__(16) __half g_b  [(size_t)NPAD * 256];   // layer2 input fp16
__device__ __align__(16) __half g_w1hi[256 * 256];
__device__ __align__(16) __half g_w1lo[256 * 256];
__device__ __align__(16) __half g_w2hi[256 * 256];
__device__ __align__(16) __half g_w2lo[256 * 256];
__device__ int g_rowptr[NNODES + 1];
__device__ int g_wix[NNODES];
__device__ int g_srcidx[NEDGES];
__device__ int g_bsum[SCAN_BLOCKS];
__device__ int g_boff[SCAN_BLOCKS];
__device__ int g_is64;

__device__ __forceinline__ uint32_t smem_u32(const void* p) {
    uint32_t a;
    asm("{ .reg .u64 t; cvta.to.shared.u64 t, %1; cvt.u32.u64 %0, t; }"
        : "=r"(a) : "l"(p));
    return a;
}

#define MMA_F16(c, a, b0, b1) \
    asm volatile("mma.sync.aligned.m16n8k16.row.col.f32.f16.f16.f32 " \
        "{%0,%1,%2,%3}, {%4,%5,%6,%7}, {%8,%9}, {%0,%1,%2,%3};" \
        : "+f"((c)[0]), "+f"((c)[1]), "+f"((c)[2]), "+f"((c)[3]) \
        : "r"((a)[0]), "r"((a)[1]), "r"((a)[2]), "r"((a)[3]), "r"(b0), "r"(b1))

#define CP_ASYNC16(dst, src) \
    asm volatile("cp.async.cg.shared.global [%0], [%1], 16;" \
                 :: "r"(dst), "l"(src) : "memory")
#define CP_COMMIT() asm volatile("cp.async.commit_group;" ::: "memory")
#define CP_WAIT0()  asm volatile("cp.async.wait_group 0;" ::: "memory")

// ---------------- edge index decode ----------------
__device__ __forceinline__ void load_edge(const void* ei, int e, int& s, int& t) {
    if (g_is64) {
        const long long* e64 = (const long long*)ei;
        s = (int)e64[e];
        t = (int)e64[(size_t)NEDGES + e];
    } else {
        const int* e32 = (const int*)ei;
        s = e32[e];
        t = e32[(size_t)NEDGES + e];
    }
}

__global__ void detect_kernel(const int* __restrict__ ei32) {
    __shared__ int sOr;
    if (threadIdx.x == 0) sOr = 0;
    __syncthreads();
    int acc = 0;
    for (int i = threadIdx.x; i < 2048; i += blockDim.x) acc |= ei32[2 * i + 1];
    atomicOr(&sOr, acc);
    __syncthreads();
    if (threadIdx.x == 0) g_is64 = (sOr == 0) ? 1 : 0;
}

// ---------------- CSR build (by target) ----------------
__global__ void zero_wix() {
    int i = blockIdx.x * blockDim.x + threadIdx.x;
    if (i < NNODES) g_wix[i] = 0;
}

__global__ void count_kernel(const void* __restrict__ ei) {
    int e = blockIdx.x * blockDim.x + threadIdx.x;
    if (e >= NEDGES) return;
    int s, t;
    load_edge(ei, e, s, t);
    if ((unsigned)s >= NNODES || (unsigned)t >= NNODES) return;
    atomicAdd(&g_wix[t], 1);
}

__global__ void blocksum_kernel() {
    __shared__ int red[32];
    int idx = blockIdx.x * 1024 + threadIdx.x;
    int v = (idx < NNODES) ? g_wix[idx] : 0;
#pragma unroll
    for (int o = 16; o > 0; o >>= 1) v += __shfl_down_sync(0xFFFFFFFFu, v, o);
    if ((threadIdx.x & 31) == 0) red[threadIdx.x >> 5] = v;
    __syncthreads();
    if (threadIdx.x < 32) {
        int w = red[threadIdx.x];
#pragma unroll
        for (int o = 16; o > 0; o >>= 1) w += __shfl_down_sync(0xFFFFFFFFu, w, o);
        if (threadIdx.x == 0) g_bsum[blockIdx.x] = w;
    }
}

__global__ void scan_bsum() {
    __shared__ int s[SCAN_BLOCKS];
    int tid = threadIdx.x;
    if (tid < SCAN_BLOCKS) s[tid] = g_bsum[tid];
    __syncthreads();
    if (tid == 0) {
        int run = 0;
        for (int i = 0; i < SCAN_BLOCKS; ++i) {
            g_boff[i] = run;
            run += s[i];
        }
        g_rowptr[NNODES] = run;
    }
}

__global__ void rowptr_kernel() {
    __shared__ int sc[1024];
    int tid = threadIdx.x;
    int idx = blockIdx.x * 1024 + tid;
    int v = (idx < NNODES) ? g_wix[idx] : 0;
    sc[tid] = v;
    __syncthreads();
#pragma unroll
    for (int off = 1; off < 1024; off <<= 1) {
        int u = (tid >= off) ? sc[tid - off] : 0;
        __syncthreads();
        sc[tid] += u;
        __syncthreads();
    }
    if (idx < NNODES) {
        int excl = sc[tid] - v + g_boff[blockIdx.x];
        g_rowptr[idx] = excl;
        g_wix[idx] = excl;
    }
}

__global__ void scatter_kernel(const void* __restrict__ ei) {
    int e = blockIdx.x * blockDim.x + threadIdx.x;
    if (e >= NEDGES) return;
    int s, t;
    load_edge(ei, e, s, t);
    if ((unsigned)s >= NNODES || (unsigned)t >= NNODES) return;
    int pos = atomicAdd(&g_wix[t], 1);
    g_srcidx[pos] = s;
}

// ---------------- x -> fp16 convert ----------------
__global__ void xconv_kernel(const float* __restrict__ x) {
    int idx = blockIdx.x * 256 + threadIdx.x;   // float4 index, NNODES*32 total
    if (idx >= NNODES * 32) return;
    float4 v = ((const float4*)x)[idx];
    __half hm[4] = {__float2half(v.x), __float2half(v.y),
                    __float2half(v.z), __float2half(v.w)};
    *(uint2*)(g_xh + (size_t)idx * 4) = *(const uint2*)hm;
}

// ---------------- gather aggregation: one warp per node, fp16 rows ----------------
// phase 0: mean of g_xh rows -> fp16 cols [0,128); g_xh[node] -> cols [128,256)
// phase 1: mean of g_p rows -> out[node] += mean
__global__ void gather_kernel(float* __restrict__ out, int phase) {
    int node = (int)(((size_t)blockIdx.x * blockDim.x + threadIdx.x) >> 5);
    int lane = threadIdx.x & 31;
    if (node >= NNODES) return;
    int beg = g_rowptr[node];
    int end = g_rowptr[node + 1];
    const __half* src = (phase == 0) ? g_xh : g_p;

    float a0 = 0.f, a1 = 0.f, a2 = 0.f, a3 = 0.f;
    int i = beg;
    for (; i + 7 < end; i += 8) {
        int sx[8];
#pragma unroll
        for (int u = 0; u < 8; ++u) sx[u] = g_srcidx[i + u];
        uint2 v[8];
#pragma unroll
        for (int u = 0; u < 8; ++u)
            v[u] = *(const uint2*)(src + ((size_t)sx[u] << 7) + lane * 4);
#pragma unroll
        for (int u = 0; u < 8; ++u) {
            float2 f0 = __half22float2(*(const __half2*)&v[u].x);
            float2 f1 = __half22float2(*(const __half2*)&v[u].y);
            a0 += f0.x; a1 += f0.y; a2 += f1.x; a3 += f1.y;
        }
    }
    if (i + 3 < end) {
        int sx[4];
#pragma unroll
        for (int u = 0; u < 4; ++u) sx[u] = g_srcidx[i + u];
        uint2 v[4];
#pragma unroll
        for (int u = 0; u < 4; ++u)
            v[u] = *(const uint2*)(src + ((size_t)sx[u] << 7) + lane * 4);
#pragma unroll
        for (int u = 0; u < 4; ++u) {
            float2 f0 = __half22float2(*(const __half2*)&v[u].x);
            float2 f1 = __half22float2(*(const __half2*)&v[u].y);
            a0 += f0.x; a1 += f0.y; a2 += f1.x; a3 += f1.y;
        }
        i += 4;
    }
    for (; i < end; ++i) {
        uint2 v0 = *(const uint2*)(src + ((size_t)g_srcidx[i] << 7) + lane * 4);
        float2 f0 = __half22float2(*(const __half2*)&v0.x);
        float2 f1 = __half22float2(*(const __half2*)&v0.y);
        a0 += f0.x; a1 += f0.y; a2 += f1.x; a3 += f1.y;
    }
    float rdeg = 1.0f / fmaxf((float)(end - beg), 1.0f);

    if (phase == 0) {
        __half hm[4] = {__float2half(a0 * rdeg), __float2half(a1 * rdeg),
                        __float2half(a2 * rdeg), __float2half(a3 * rdeg)};
        *(uint2*)(g_a + (size_t)node * 256 + lane * 4) = *(const uint2*)hm;
        // fused xsplit: copy x[node] fp16 -> cols [128,256)
        uint2 xr = *(const uint2*)(g_xh + ((size_t)node << 7) + lane * 4);
        *(uint2*)(g_a + (size_t)node * 256 + 128 + lane * 4) = xr;
    } else {
        float4* op = (float4*)out + (size_t)node * 32 + lane;
        float4 o = *op;
        o.x += a0 * rdeg; o.y += a1 * rdeg;
        o.z += a2 * rdeg; o.w += a3 * rdeg;
        *op = o;
    }
}

// zero the 96 pad rows of g_a (all 256 cols)
__global__ void pad_kernel() {
    int r = NNODES + blockIdx.x;            // 96 blocks
    int q = threadIdx.x;                     // 64 threads x 4 halves
    uint2 z = make_uint2(0u, 0u);
    *(uint2*)(g_a + (size_t)r * 256 + q * 4) = z;
}

__global__ void prep_weights(const float* __restrict__ W1l, const float* __restrict__ W1r,
                             const float* __restrict__ W2l, const float* __restrict__ W2r) {
    int j = blockIdx.x;    // out dim
    int k = threadIdx.x;   // in dim
    float w1 = (k < 128) ? W1l[j * 128 + k] : W1r[j * 128 + (k - 128)];
    float w2 = (j < 128) ? W2l[j * 256 + k] : W2r[(j - 128) * 256 + k];
    __half h1 = __float2half(w1);
    __half h2 = __float2half(w2);
    g_w1hi[j * 256 + k] = h1;
    g_w1lo[j * 256 + k] = __float2half(w1 - __half2float(h1));
    g_w2hi[j * 256 + k] = h2;
    g_w2lo[j * 256 + k] = __float2half(w2 - __half2float(h2));
}

// ---------------- mma.sync GEMM: 2-term fp16 (A single, W hi/lo) ----------------
#define TILE_B   10240      // 128 * 80
#define STAGE_B  30720
#define GEMM_SMEM 61440

__device__ __forceinline__ void cp_stage(uint32_t sb,
    const __half* A, const __half* Whi, const __half* Wlo,
    int row0, int nbase, int kt, int st, int tid) {
#pragma unroll
    for (int i = 0; i < 6; ++i) {
        int c = i * 256 + tid;          // 0..1535
        int tile = c >> 9;              // 0:A 1:Whi 2:Wlo
        int idx  = c & 511;
        int row  = idx >> 2;
        int kc   = idx & 3;
        uint32_t dst = sb + st * STAGE_B + tile * TILE_B
                     + (uint32_t)(row * 80 + kc * 16);
        const __half* g;
        if (tile == 0)      g = A   + (size_t)(row0 + row) * 256;
        else if (tile == 1) g = Whi + (size_t)(nbase + row) * 256;
        else                g = Wlo + (size_t)(nbase + row) * 256;
        g += kt * 32 + kc * 8;
        CP_ASYNC16(dst, g);
    }
}

__global__ void __launch_bounds__(256, 2) gemm_mma(int layer,
                                                   const float* __restrict__ b1v,
                                                   const float* __restrict__ b2v,
                                                   float* __restrict__ dout) {
    extern __shared__ char dsm[];
    int tid = threadIdx.x, lane = tid & 31, wid = tid >> 5;
    int row0 = blockIdx.x * 128;
    int by   = blockIdx.y;
    int nbase = by * 128;

    const __half* A   = (layer == 1) ? g_a : g_b;
    const __half* Whi = (layer == 1) ? g_w1hi : g_w2hi;
    const __half* Wlo = (layer == 1) ? g_w1lo : g_w2lo;

    uint32_t sb = smem_u32(dsm);
    int mrow = (wid >> 1) * 32;
    int ncol = (wid & 1) * 64;

    float acc[2][8][4];
#pragma unroll
    for (int mt = 0; mt < 2; ++mt)
#pragma unroll
        for (int j = 0; j < 8; ++j)
#pragma unroll
            for (int q = 0; q < 4; ++q) acc[mt][j][q] = 0.f;

    cp_stage(sb, A, Whi, Wlo, row0, nbase, 0, 0, tid);
    CP_COMMIT();

    for (int kt = 0; kt < 8; ++kt) {
        int st = kt & 1;
        CP_WAIT0();
        __syncthreads();
        if (kt < 7) {
            cp_stage(sb, A, Whi, Wlo, row0, nbase, kt + 1, st ^ 1, tid);
            CP_COMMIT();
        }
        const char* sa = dsm + st * STAGE_B;
#pragma unroll
        for (int ks = 0; ks < 2; ++ks) {
            uint32_t a_base = (uint32_t)((mrow + (lane >> 2)) * 80
                                         + (lane & 3) * 4 + ks * 32);
            uint32_t ah[2][4];
#pragma unroll
            for (int mt = 0; mt < 2; ++mt) {
                uint32_t o = a_base + mt * 1280;
                ah[mt][0] = *(const uint32_t*)(sa + o);
                ah[mt][1] = *(const uint32_t*)(sa + o + 640);
                ah[mt][2] = *(const uint32_t*)(sa + o + 16);
                ah[mt][3] = *(const uint32_t*)(sa + o + 656);
            }
            uint32_t b_base = (uint32_t)((ncol + (lane >> 2)) * 80
                                         + (lane & 3) * 4 + ks * 32);
#pragma unroll
            for (int j = 0; j < 8; ++j) {
                uint32_t o = b_base + j * 640;
                uint32_t bh0 = *(const uint32_t*)(sa + TILE_B + o);
                uint32_t bh1 = *(const uint32_t*)(sa + TILE_B + o + 16);
                uint32_t bl0 = *(const uint32_t*)(sa + 2 * TILE_B + o);
                uint32_t bl1 = *(const uint32_t*)(sa + 2 * TILE_B + o + 16);
#pragma unroll
                for (int mt = 0; mt < 2; ++mt) {
                    MMA_F16(acc[mt][j], ah[mt], bh0, bh1);
                    MMA_F16(acc[mt][j], ah[mt], bl0, bl1);
                }
            }
        }
        __syncthreads();
    }

    int r_base  = row0 + mrow + (lane >> 2);
    int cl_base = ncol + (lane & 3) * 2;
    if (layer == 1) {
        // h = relu(acc + b1) -> fp16 into g_b (layer2 input)
#pragma unroll
        for (int mt = 0; mt < 2; ++mt)
#pragma unroll
            for (int j = 0; j < 8; ++j) {
                int gn = nbase + cl_base + j * 8;
                float bx0 = b1v[gn], bx1 = b1v[gn + 1];
#pragma unroll
                for (int hh = 0; hh < 2; ++hh) {
                    int r = r_base + mt * 16 + hh * 8;
                    float v0 = fmaxf(acc[mt][j][hh * 2]     + bx0, 0.f);
                    float v1 = fmaxf(acc[mt][j][hh * 2 + 1] + bx1, 0.f);
                    __half hp[2] = {__float2half(v0), __float2half(v1)};
                    *(uint32_t*)(g_b + (size_t)r * 256 + gn) = *(const uint32_t*)hp;
                }
            }
    } else {
#pragma unroll
        for (int mt = 0; mt < 2; ++mt)
#pragma unroll
            for (int j = 0; j < 8; ++j) {
                int cl = cl_base + j * 8;
#pragma unroll
                for (int hh = 0; hh < 2; ++hh) {
                    int r = r_base + mt * 16 + hh * 8;
                    float v0 = acc[mt][j][hh * 2];
                    float v1 = acc[mt][j][hh * 2 + 1];
                    if (by == 0) {
                        __half hp[2] = {__float2half(v0), __float2half(v1)};
                        *(uint32_t*)(g_p + (size_t)r * 128 + cl) = *(const uint32_t*)hp;
                    } else if (r < NNODES) {
                        float2 w = make_float2(v0 + b2v[cl], v1 + b2v[cl + 1]);
                        *(float2*)(dout + (size_t)r * 128 + cl) = w;
                    }
                }
            }
    }
}

extern "C" void kernel_launch(void* const* d_in, const int* in_sizes, int n_in,
                              void* d_out, int out_size) {
    const float* x   = (const float*)d_in[0];
    const void*  ei  = d_in[1];
    const float* W1l = (const float*)d_in[2];
    const float* b1  = (const float*)d_in[3];
    const float* W1r = (const float*)d_in[4];
    const float* W2l = (const float*)d_in[5];
    const float* b2  = (const float*)d_in[6];
    const float* W2r = (const float*)d_in[7];
    float* out = (float*)d_out;

    cudaFuncSetAttribute(gemm_mma, cudaFuncAttributeMaxDynamicSharedMemorySize,
                         GEMM_SMEM);

    // CSR build (once) + weight prep + x fp16 convert
    detect_kernel<<<1, 256>>>((const int*)ei);
    zero_wix<<<(NNODES + 255) / 256, 256>>>();
    count_kernel<<<(NEDGES + 255) / 256, 256>>>(ei);
    xconv_kernel<<<12500, 256>>>(x);
    blocksum_kernel<<<SCAN_BLOCKS, 1024>>>();
    scan_bsum<<<1, 128>>>();
    rowptr_kernel<<<SCAN_BLOCKS, 1024>>>();
    scatter_kernel<<<(NEDGES + 255) / 256, 256>>>(ei);
    prep_weights<<<256, 256>>>(W1l, W1r, W2l, W2r);
    pad_kernel<<<NPAD - NNODES, 64>>>();

    // layer 1: gather-mean(x fp16)+xsplit -> g_a, then GEMM -> g_b
    gather_kernel<<<12500, 256>>>(out, 0);
    gemm_mma<<<dim3(NBM, 2), 256, GEMM_SMEM>>>(1, b1, b2, out);

    // layer 2: GEMM (p fp16 -> g_p, r + b2 -> out), then out += gather-mean(p)
    gemm_mma<<<dim3(NBM, 2), 256, GEMM_SMEM>>>(2, b1, b2, out);
    gather_kernel<<<12500, 256>>>(out, 1);
}